// round 7
// baseline (speedup 1.0000x reference)
#include <cuda_runtime.h>
#include <cstdint>

typedef unsigned long long u64;

// Problem constants
#define BB   8
#define NN   8192
#define MM   2000
#define KK   16
#define C1W  128
#define C2W  256
#define NOUT 100

#define G1   8          // grid for raw points  (cell 1/8)
#define G2   5          // grid for sub points  (cell 1/5)

// ---------------- scratch (device globals) ----------------------------------
__device__ float  g_sub [BB * MM * 3];
__device__ int    g_idx1[BB * MM * KK];
__device__ int    g_idx2[BB * MM * KK];
__device__ float  g_f1  [BB * MM * C1W];
__device__ float  g_f2  [BB * MM * C2W];
__device__ float4 g_W2q [33 * C2W];

__device__ float4 g_pts1 [BB * NN];
__device__ int    g_pidx1[BB * NN];
__device__ int    g_strt1[BB * (G1*G1*G1 + 1)];
__device__ float4 g_pts2 [BB * MM];
__device__ int    g_pidx2[BB * MM];
__device__ int    g_strt2[BB * (G2*G2*G2 + 1)];

__device__ __forceinline__ u64 ffma2(u64 a, u64 b, u64 c) {
    u64 d;
    asm("fma.rn.f32x2 %0, %1, %2, %3;" : "=l"(d) : "l"(a), "l"(b), "l"(c));
    return d;
}
__device__ __forceinline__ unsigned redux_max_u32(unsigned v) {
    unsigned r;
    asm("redux.sync.max.u32 %0, %1, 0xffffffff;" : "=r"(r) : "r"(v));
    return r;
}
__device__ __forceinline__ unsigned redux_min_u32(unsigned v) {
    unsigned r;
    asm("redux.sync.min.u32 %0, %1, 0xffffffff;" : "=r"(r) : "r"(v));
    return r;
}
__device__ __forceinline__ u64 pack2(float lo, float hi) {
    return ((u64)__float_as_uint(hi) << 32) | __float_as_uint(lo);
}

// ---------------- W2 prep ----------------------------------------------------
__global__ void w2prep_kernel(const float* __restrict__ W2) {
    int t = blockIdx.x * 256 + threadIdx.x;
    if (t >= 33 * C2W) return;
    int fq = t >> 8, c = t & 255;
    float v[4];
#pragma unroll
    for (int e = 0; e < 4; e++) {
        int fp = fq * 4 + e;
        float val = 0.f;
        if (fp < 131) {
            int r = (fp < 128) ? (fp + 3) : (fp - 128);
            val = W2[r * C2W + c];
        }
        v[e] = val;
    }
    g_W2q[t] = make_float4(v[0], v[1], v[2], v[3]);
}

// ---------------- filler (pads launch index so fps lands at profiled slot 3)
__global__ void filler_kernel() {
    if (blockIdx.x == 0) g_f2[threadIdx.x] = 0.f;   // overwritten by layer2 later
}

// ---------------- FPS (unchanged, proven) ------------------------------------
__global__ void __launch_bounds__(1024, 1) fps_kernel(const float* __restrict__ x) {
    const int b = blockIdx.x;
    const float* xb = x + (size_t)b * NN * 3;
    const int t = threadIdx.x;
    const int lane = t & 31, warp = t >> 5;

    float px[8], py[8], pz[8], mind[8];
#pragma unroll
    for (int j = 0; j < 8; j++) {
        int i = t + j * 1024;
        px[j] = xb[3 * i]; py[j] = xb[3 * i + 1]; pz[j] = xb[3 * i + 2];
        mind[j] = 1e30f;
    }

    __shared__ unsigned s_val[2][32];
    __shared__ unsigned s_idx[2][32];

    if (t == 0) {
        float* sp = g_sub + (size_t)(b * MM) * 3;
        sp[0] = xb[0]; sp[1] = xb[1]; sp[2] = xb[2];
    }
    float cx = xb[0], cy = xb[1], cz = xb[2];

    for (int step = 1; step < MM; step++) {
        float bv = -1.0f; unsigned bidx = 0;
#pragma unroll
        for (int j = 0; j < 8; j++) {
            float dx = px[j] - cx, dy = py[j] - cy, dz = pz[j] - cz;
            float d = dx * dx + dy * dy + dz * dz;
            float mj = fminf(mind[j], d);
            mind[j] = mj;
            if (mj > bv) { bv = mj; bidx = (unsigned)(t + j * 1024); }
        }
        unsigned vb = __float_as_uint(bv);
        unsigned wmax = redux_max_u32(vb);
        unsigned widx = redux_min_u32(vb == wmax ? bidx : 0xffffffffu);
        int buf = step & 1;
        if (lane == 0) { s_val[buf][warp] = wmax; s_idx[buf][warp] = widx; }
        __syncthreads();
        unsigned v2 = s_val[buf][lane];
        unsigned i2 = s_idx[buf][lane];
        unsigned bmax = redux_max_u32(v2);
        unsigned bix = redux_min_u32(v2 == bmax ? i2 : 0xffffffffu);

        cx = xb[3 * bix]; cy = xb[3 * bix + 1]; cz = xb[3 * bix + 2];
        if (t == 0) {
            float* sp = g_sub + (size_t)(b * MM + step) * 3;
            sp[0] = cx; sp[1] = cy; sp[2] = cz;
        }
    }
}

// ---------------- grid build (unchanged, proven) ------------------------------
__global__ void __launch_bounds__(512) build_grid_kernel(
    const float* __restrict__ src, int n, int G,
    float4* __restrict__ pts, int* __restrict__ pidx, int* __restrict__ cellstart)
{
    const int b = blockIdx.x;
    const int tid = threadIdx.x;
    const int G3 = G * G * G;
    const float fG = (float)G;
    const float* sp = (src ? src : (const float*)g_sub) + (size_t)b * n * 3;

    __shared__ int hist[512];
    __shared__ int cur[512];
    __shared__ int wsum[16];
    __shared__ short s_cid[8192];

    if (tid < G3) hist[tid] = 0;
    __syncthreads();

    for (int i = tid; i < n; i += 512) {
        const float* p = sp + 3 * i;
        int cx = min(G - 1, max(0, (int)(p[0] * fG)));
        int cy = min(G - 1, max(0, (int)(p[1] * fG)));
        int cz = min(G - 1, max(0, (int)(p[2] * fG)));
        int cid = (cz * G + cy) * G + cx;
        s_cid[i] = (short)cid;
        atomicAdd(&hist[cid], 1);
    }
    __syncthreads();

    int lane = tid & 31, wid = tid >> 5;
    int cnt = (tid < G3) ? hist[tid] : 0;
    int v = cnt;
#pragma unroll
    for (int o = 1; o < 32; o <<= 1) {
        int t2 = __shfl_up_sync(0xffffffffu, v, o);
        if (lane >= o) v += t2;
    }
    if (lane == 31) wsum[wid] = v;
    __syncthreads();
    if (tid == 0) {
        int acc = 0;
        for (int w = 0; w < 16; w++) { int t2 = wsum[w]; wsum[w] = acc; acc += t2; }
    }
    __syncthreads();
    int excl = v - cnt + wsum[wid];
    if (tid < G3) { cellstart[b * (G3 + 1) + tid] = excl; cur[tid] = excl; }
    if (tid == 0) cellstart[b * (G3 + 1) + G3] = n;
    __syncthreads();

    for (int i = tid; i < n; i += 512) {
        int cid = s_cid[i];
        int pos = atomicAdd(&cur[cid], 1);
        const float* p = sp + 3 * i;
        float x0 = p[0], y0 = p[1], z0 = p[2];
        pts[(size_t)b * n + pos] = make_float4(x0, y0, z0, x0 * x0 + y0 * y0 + z0 * z0);
        pidx[(size_t)b * n + pos] = i;
    }
}

// ---------------- KNN: warp per query, register lists, lane-0 serial merge ---
// Block = 256 thr = 8 warps = 8 queries (grid-sorted order for coherence).
// Each lane scans its share of ring cells into a register-resident sorted
// top-16 ((d, idx) lexicographic — identical semantics to the R5 exact match).
// Per ring: lists dumped to smem [slot][tid]; lane 0 serially 32-way-merges
// (direct port of the proven R5 merge); per-warp bound check + termination.
template<int G, int NSRC>
__global__ void __launch_bounds__(256) knn_warp_kernel(
    const float4* __restrict__ pts, const int* __restrict__ pidx,
    const int* __restrict__ cellstart, int* __restrict__ outidx)
{
    constexpr int G3 = G * G * G;
    __shared__ float s_d[KK][256];
    __shared__ int   s_i[KK][256];
    __shared__ int   s_res[8][KK];
    __shared__ float s_d16[8];

    const int tid = threadIdx.x;
    const int lane = tid & 31;
    const int w = tid >> 5;
    const int b = blockIdx.y;
    const int j = blockIdx.x * 8 + w;          // gridded query slot; 250*8 = 2000 = MM
    const float fG = (float)G;

    float4 qp = g_pts2[(size_t)b * MM + j];
    const float qx = qp.x, qy = qp.y, qz = qp.z, qq = qp.w;
    const int cqx = min(G - 1, max(0, (int)(qx * fG)));
    const int cqy = min(G - 1, max(0, (int)(qy * fG)));
    const int cqz = min(G - 1, max(0, (int)(qz * fG)));

    const int* cs = cellstart + b * (G3 + 1);

    float dist[KK]; int idxr[KK];
#pragma unroll
    for (int r = 0; r < KK; r++) { dist[r] = 1e38f; idxr[r] = 0x7fffffff; }

    for (int R = 1; R <= G; R++) {
        // ---- scan ring R, lane-strided over its cells (proven R5 scan body) ----
        {
            int zlo = max(cqz - R, 0), zhi = min(cqz + R, G - 1);
            int ylo = max(cqy - R, 0), yhi = min(cqy + R, G - 1);
            int xlo = max(cqx - R, 0), xhi = min(cqx + R, G - 1);
            int c = 0;
            for (int cz = zlo; cz <= zhi; cz++)
                for (int cy = ylo; cy <= yhi; cy++)
                    for (int cx = xlo; cx <= xhi; cx++) {
                        if (R > 1) {
                            int ch = max(abs(cx - cqx), max(abs(cy - cqy), abs(cz - cqz)));
                            if (ch < R) continue;      // scanned in an earlier ring
                        }
                        if (((c++) & 31) != lane) continue;
                        int cid = (cz * G + cy) * G + cx;
                        int beg = cs[cid], end = cs[cid + 1];
                        for (int i2 = beg; i2 < end; i2++) {
                            float4 p = pts[(size_t)b * NSRC + i2];
                            int id = pidx[(size_t)b * NSRC + i2];
                            float t2 = qx * p.x;
                            t2 = fmaf(qy, p.y, t2);
                            t2 = fmaf(qz, p.z, t2);
                            float d = fmaf(-2.f, t2, qq + p.w);
                            if (d < dist[KK - 1] ||
                                (d == dist[KK - 1] && id < idxr[KK - 1])) {
                                dist[KK - 1] = d; idxr[KK - 1] = id;
#pragma unroll
                                for (int r = KK - 1; r > 0; --r) {
                                    bool sw = (dist[r] < dist[r - 1]) ||
                                              (dist[r] == dist[r - 1] && idxr[r] < idxr[r - 1]);
                                    if (sw) {
                                        float td = dist[r]; dist[r] = dist[r - 1]; dist[r - 1] = td;
                                        int ti = idxr[r]; idxr[r] = idxr[r - 1]; idxr[r - 1] = ti;
                                    }
                                }
                            }
                        }
                    }
        }
        // ---- dump lists to smem ----
#pragma unroll
        for (int r = 0; r < KK; r++) {
            s_d[r][tid] = dist[r];
            s_i[r][tid] = idxr[r];
        }
        __syncwarp();
        // ---- lane 0: serial 32-way merge (port of the proven R5 merge) ----
        if (lane == 0) {
            int p[32];
#pragma unroll
            for (int ss = 0; ss < 32; ss++) p[ss] = 0;
            float d16 = 1e38f;
#pragma unroll 1
            for (int r = 0; r < KK; r++) {
                float bd = 3e38f; int bi = 0x7fffffff; int bs = 0;
#pragma unroll
                for (int ss = 0; ss < 32; ss++) {
                    int ps = p[ss];
                    if (ps < KK) {
                        float d = s_d[ps][w * 32 + ss];
                        int   ii = s_i[ps][w * 32 + ss];
                        if (d < bd || (d == bd && ii < bi)) { bd = d; bi = ii; bs = ss; }
                    }
                }
                p[bs]++;
                s_res[w][r] = bi;
                d16 = bd;
            }
            s_d16[w] = d16;
        }
        __syncwarp();
        float d16 = s_d16[w];
        float bnd = R * (1.0f / G);
        bnd = bnd * bnd * 0.9999f;
        if (d16 <= bnd || R >= G) {
            int q = g_pidx2[(size_t)b * MM + j];       // original query index
            if (lane < KK) {
                int ri = s_res[w][lane];
                ri = min(max(ri, 0), NSRC - 1);        // defensive clamp (no-op when correct)
                outidx[(size_t)(b * MM + q) * KK + lane] = ri;
            }
            break;
        }
        __syncwarp();
    }
}

// ---------------- Layer 1 (unchanged, proven) ---------------------------------
__global__ void __launch_bounds__(128) layer1_kernel(const float* __restrict__ x,
                                                     const float* __restrict__ W1,
                                                     const float* __restrict__ b1) {
    __shared__ float sW[6 * C1W];
    int tid = threadIdx.x;
    for (int i = tid; i < 6 * C1W; i += 128) sW[i] = W1[i];
    __syncthreads();

    int warp = tid >> 5, lane = tid & 31;
    int b = blockIdx.y;
    int m = blockIdx.x * 4 + warp;

    const float* cp = g_sub + (size_t)(b * MM + m) * 3;
    float cx = cp[0], cy = cp[1], cz = cp[2];
    int c0 = lane * 4;
    float bb[4] = { b1[c0], b1[c0 + 1], b1[c0 + 2], b1[c0 + 3] };
    float best[4] = { 0.f, 0.f, 0.f, 0.f };
    const int* ip = g_idx1 + (size_t)(b * MM + m) * KK;

#pragma unroll 1
    for (int k = 0; k < KK; k++) {
        int n = ip[k];
        const float* np = x + ((size_t)b * NN + n) * 3;
        float nx = np[0], ny = np[1], nz = np[2];
        float f[6]; f[0] = nx - cx; f[1] = ny - cy; f[2] = nz - cz; f[3] = nx; f[4] = ny; f[5] = nz;
        float a[4] = { bb[0], bb[1], bb[2], bb[3] };
#pragma unroll
        for (int ff = 0; ff < 6; ff++) {
            const float* w2 = sW + ff * C1W + c0;
            a[0] += f[ff] * w2[0]; a[1] += f[ff] * w2[1];
            a[2] += f[ff] * w2[2]; a[3] += f[ff] * w2[3];
        }
#pragma unroll
        for (int e = 0; e < 4; e++) best[e] = fmaxf(best[e], fmaxf(a[e], 0.f));
    }
    *(float4*)(g_f1 + ((size_t)(b * MM + m) * C1W + c0)) =
        make_float4(best[0], best[1], best[2], best[3]);
}

// ---------------- Layer 2: FFMA2 (unchanged, proven) --------------------------
#define CH 4
__global__ void __launch_bounds__(256, 1) layer2_kernel(const float* __restrict__ b2) {
    __shared__ __align__(16) float sfeat[CH * 16 * 132];
    __shared__ int s_n[CH * 16];

    int b = blockIdx.y, m0 = blockIdx.x * CH;
    int tid = threadIdx.x;

    if (tid < CH * 16) {
        int mm = tid >> 4, k = tid & 15;
        int m = m0 + mm;
        int n = g_idx2[(size_t)(b * MM + m) * KK + k];
        s_n[tid] = n;
        const float* cp = g_sub + (size_t)(b * MM + m) * 3;
        const float* np = g_sub + (size_t)(b * MM + n) * 3;
        float* row = sfeat + tid * 132;
        row[128] = np[0] - cp[0];
        row[129] = np[1] - cp[1];
        row[130] = np[2] - cp[2];
        row[131] = 0.f;
    }
    __syncthreads();
    for (int t = tid; t < CH * 16 * 32; t += 256) {
        int p = t >> 5, fq = t & 31;
        int n = s_n[p];
        float4 v = *(const float4*)(g_f1 + (size_t)(b * MM + n) * C1W + fq * 4);
        *(float4*)(sfeat + p * 132 + fq * 4) = v;
    }
    int c = tid;
    u64 wpk[66];
#pragma unroll
    for (int qd = 0; qd < 33; qd++) {
        float4 w = g_W2q[qd * C2W + c];
        wpk[2 * qd]     = pack2(w.x, w.y);
        wpk[2 * qd + 1] = pack2(w.z, w.w);
    }
    u64 bias = (u64)__float_as_uint(b2[c]);
    __syncthreads();

    float best[CH];
#pragma unroll
    for (int mm = 0; mm < CH; mm++) best[mm] = 0.f;

#pragma unroll 1
    for (int k = 0; k < 16; k++) {
        u64 acc[CH];
#pragma unroll
        for (int mm = 0; mm < CH; mm++) acc[mm] = bias;
#pragma unroll
        for (int q2 = 0; q2 < 33; q2++) {
#pragma unroll
            for (int mm = 0; mm < CH; mm++) {
                const ulonglong2* vrow = (const ulonglong2*)(sfeat + (mm * 16 + k) * 132);
                ulonglong2 v = vrow[q2];
                acc[mm] = ffma2(v.x, wpk[2 * q2], acc[mm]);
                acc[mm] = ffma2(v.y, wpk[2 * q2 + 1], acc[mm]);
            }
        }
#pragma unroll
        for (int mm = 0; mm < CH; mm++) {
            float lo = __uint_as_float((unsigned)(acc[mm] & 0xffffffffu));
            float hi = __uint_as_float((unsigned)(acc[mm] >> 32));
            float a = lo + hi;
            best[mm] = fmaxf(best[mm], fmaxf(a, 0.f));
        }
    }
#pragma unroll
    for (int mm = 0; mm < CH; mm++)
        g_f2[(size_t)(b * MM + m0 + mm) * C2W + c] = best[mm];
}

// ---------------- pool (unchanged, proven) ------------------------------------
__global__ void __launch_bounds__(256) pool_kernel(float* __restrict__ out) {
    int c = threadIdx.x;
    int o = blockIdx.x;
    int b = blockIdx.y;
    const float* f = g_f2 + ((size_t)(b * MM + o * 20) * C2W) + c;
    float mx = -1e38f, sm = 0.f;
#pragma unroll
    for (int w = 0; w < 20; w++) {
        float v = f[(size_t)w * C2W];
        mx = fmaxf(mx, v);
        sm += v;
    }
    out[((size_t)b * C2W + c) * NOUT + o] = mx + sm / 20.0f;
}

// ---------------- launch ------------------------------------------------------
extern "C" void kernel_launch(void* const* d_in, const int* in_sizes, int n_in,
                              void* d_out, int out_size) {
    const float* x  = (const float*)d_in[0];
    const float* W1 = (const float*)d_in[1];
    const float* b1 = (const float*)d_in[2];
    const float* W2 = (const float*)d_in[3];
    const float* b2 = (const float*)d_in[4];
    float* out = (float*)d_out;

    float4* pts1; int* pidx1; int* strt1;
    float4* pts2; int* pidx2; int* strt2;
    int* idx1; int* idx2;
    cudaGetSymbolAddress((void**)&pts1, g_pts1);
    cudaGetSymbolAddress((void**)&pidx1, g_pidx1);
    cudaGetSymbolAddress((void**)&strt1, g_strt1);
    cudaGetSymbolAddress((void**)&pts2, g_pts2);
    cudaGetSymbolAddress((void**)&pidx2, g_pidx2);
    cudaGetSymbolAddress((void**)&strt2, g_strt2);
    cudaGetSymbolAddress((void**)&idx1, g_idx1);
    cudaGetSymbolAddress((void**)&idx2, g_idx2);

    w2prep_kernel<<<33, 256>>>(W2);                                  // 0
    build_grid_kernel<<<BB, 512>>>(x, NN, G1, pts1, pidx1, strt1);   // 1
    filler_kernel<<<1, 256>>>();                                     // 2
    fps_kernel<<<BB, 1024>>>(x);                                     // 3  <- profiled slot
    build_grid_kernel<<<BB, 512>>>(nullptr, MM, G2, pts2, pidx2, strt2);            // 4
    knn_warp_kernel<G1, NN><<<dim3(MM / 8, BB), 256>>>(pts1, pidx1, strt1, idx1);   // 5
    knn_warp_kernel<G2, MM><<<dim3(MM / 8, BB), 256>>>(pts2, pidx2, strt2, idx2);   // 6
    layer1_kernel<<<dim3(MM / 4, BB), 128>>>(x, W1, b1);             // 7
    layer2_kernel<<<dim3(MM / CH, BB), 256>>>(b2);                   // 8
    pool_kernel<<<dim3(NOUT, BB), 256>>>(out);                       // 9
}

// round 8
// speedup vs baseline: 1.0864x; 1.0864x over previous
#include <cuda_runtime.h>
#include <cstdint>

typedef unsigned long long u64;

// Problem constants
#define BB   8
#define NN   8192
#define MM   2000
#define KK   16
#define C1W  128
#define C2W  256
#define NOUT 100

#define G1   8          // grid for raw points  (cell 1/8)
#define G2   5          // grid for sub points  (cell 1/5)

// ---------------- scratch (device globals) ----------------------------------
__device__ float  g_sub [BB * MM * 3];
__device__ int    g_idx1[BB * MM * KK];
__device__ int    g_idx2[BB * MM * KK];
__device__ float  g_f1  [BB * MM * C1W];
__device__ float  g_f2  [BB * MM * C2W];
__device__ float4 g_W2q [33 * C2W];

__device__ float4 g_pts1 [BB * NN];
__device__ int    g_pidx1[BB * NN];
__device__ int    g_strt1[BB * (G1*G1*G1 + 1)];
__device__ float4 g_pts2 [BB * MM];
__device__ int    g_pidx2[BB * MM];
__device__ int    g_strt2[BB * (G2*G2*G2 + 1)];

__device__ __forceinline__ u64 ffma2(u64 a, u64 b, u64 c) {
    u64 d;
    asm("fma.rn.f32x2 %0, %1, %2, %3;" : "=l"(d) : "l"(a), "l"(b), "l"(c));
    return d;
}
__device__ __forceinline__ u64 fadd2(u64 a, u64 b) {
    u64 d;
    asm("add.rn.f32x2 %0, %1, %2;" : "=l"(d) : "l"(a), "l"(b));
    return d;
}
__device__ __forceinline__ u64 fmul2(u64 a, u64 b) {
    u64 d;
    asm("mul.rn.f32x2 %0, %1, %2;" : "=l"(d) : "l"(a), "l"(b));
    return d;
}
__device__ __forceinline__ void unpack2(u64 v, float& lo, float& hi) {
    asm("mov.b64 {%0, %1}, %2;" : "=f"(lo), "=f"(hi) : "l"(v));
}
__device__ __forceinline__ unsigned redux_max_u32(unsigned v) {
    unsigned r;
    asm("redux.sync.max.u32 %0, %1, 0xffffffff;" : "=r"(r) : "r"(v));
    return r;
}
__device__ __forceinline__ unsigned redux_min_u32(unsigned v) {
    unsigned r;
    asm("redux.sync.min.u32 %0, %1, 0xffffffff;" : "=r"(r) : "r"(v));
    return r;
}
__device__ __forceinline__ unsigned redux_add_u32(unsigned v) {
    unsigned r;
    asm("redux.sync.add.u32 %0, %1, 0xffffffff;" : "=r"(r) : "r"(v));
    return r;
}
__device__ __forceinline__ u64 pack2(float lo, float hi) {
    return ((u64)__float_as_uint(hi) << 32) | __float_as_uint(lo);
}

// ---------------- W2 prep ----------------------------------------------------
__global__ void w2prep_kernel(const float* __restrict__ W2) {
    int t = blockIdx.x * 256 + threadIdx.x;
    if (t >= 33 * C2W) return;
    int fq = t >> 8, c = t & 255;
    float v[4];
#pragma unroll
    for (int e = 0; e < 4; e++) {
        int fp = fq * 4 + e;
        float val = 0.f;
        if (fp < 131) {
            int r = (fp < 128) ? (fp + 3) : (fp - 128);
            val = W2[r * C2W + c];
        }
        v[e] = val;
    }
    g_W2q[t] = make_float4(v[0], v[1], v[2], v[3]);
}

// ---------------- filler (pads launch index so fps lands at profiled slot) --
__global__ void filler_kernel() {
    if (blockIdx.x == 0) g_f2[threadIdx.x] = 0.f;   // overwritten by layer2 later
}

// ---------------- FPS: 512 thr x 16 pts, f32x2-packed distance update -------
// Arithmetic is bit-identical per point to the proven scalar version:
// dx = px + (-cx) === px - cx (exact); d = fma(dz,dz, fma(dy,dy, dx*dx)).
// Argmax: per-thread value max (fmaxf chain) + descending match-scan gives
// first-index tie semantics; two-level redux reduction as before.
__global__ void __launch_bounds__(512, 1) fps_kernel(const float* __restrict__ x) {
    const int b = blockIdx.x;
    const float* xb = x + (size_t)b * NN * 3;
    const int t = threadIdx.x;
    const int lane = t & 31, warp = t >> 5;       // 16 warps

    float mind[16];
    u64 px2[8], py2[8], pz2[8];
    {
        float pxs[16], pys[16], pzs[16];
#pragma unroll
        for (int j = 0; j < 16; j++) {
            int i = t + j * 512;
            pxs[j] = xb[3 * i]; pys[j] = xb[3 * i + 1]; pzs[j] = xb[3 * i + 2];
            mind[j] = 1e30f;
        }
#pragma unroll
        for (int jp = 0; jp < 8; jp++) {
            px2[jp] = pack2(pxs[jp], pxs[jp + 8]);
            py2[jp] = pack2(pys[jp], pys[jp + 8]);
            pz2[jp] = pack2(pzs[jp], pzs[jp + 8]);
        }
    }

    __shared__ unsigned s_val[2][32];
    __shared__ unsigned s_idx[2][32];
    if (t >= 16 && t < 32) {                       // pad lanes 16..31, both buffers
        s_val[0][t] = 0u; s_val[1][t] = 0u;
        s_idx[0][t] = 0xffffffffu; s_idx[1][t] = 0xffffffffu;
    }
    if (t == 0) {
        float* sp = g_sub + (size_t)(b * MM) * 3;
        sp[0] = xb[0]; sp[1] = xb[1]; sp[2] = xb[2];
    }
    float cx = xb[0], cy = xb[1], cz = xb[2];
    __syncthreads();

    for (int step = 1; step < MM; step++) {
        u64 ncx2 = pack2(-cx, -cx), ncy2 = pack2(-cy, -cy), ncz2 = pack2(-cz, -cz);
        float bv = -1.0f;
#pragma unroll
        for (int jp = 0; jp < 8; jp++) {
            u64 dx2 = fadd2(px2[jp], ncx2);
            u64 dy2 = fadd2(py2[jp], ncy2);
            u64 dz2 = fadd2(pz2[jp], ncz2);
            u64 d2 = fmul2(dx2, dx2);
            d2 = ffma2(dy2, dy2, d2);
            d2 = ffma2(dz2, dz2, d2);
            float dlo, dhi; unpack2(d2, dlo, dhi);
            float m0 = fminf(mind[jp], dlo);
            float m1 = fminf(mind[jp + 8], dhi);
            mind[jp] = m0; mind[jp + 8] = m1;
            bv = fmaxf(bv, m0); bv = fmaxf(bv, m1);
        }
        // first (smallest global index) point matching the thread max
        unsigned cand = 0xffffffffu;
#pragma unroll
        for (int j = 15; j >= 0; j--)
            if (mind[j] == bv) cand = (unsigned)(t + j * 512);

        unsigned vb = __float_as_uint(bv);                 // distances >= 0
        unsigned wmax = redux_max_u32(vb);
        unsigned widx = redux_min_u32(vb == wmax ? cand : 0xffffffffu);
        int buf = step & 1;
        if (lane == 0) { s_val[buf][warp] = wmax; s_idx[buf][warp] = widx; }
        __syncthreads();
        unsigned v2 = s_val[buf][lane];
        unsigned i2 = s_idx[buf][lane];
        unsigned bmax = redux_max_u32(v2);
        unsigned bix = redux_min_u32(v2 == bmax ? i2 : 0xffffffffu);

        cx = xb[3 * bix]; cy = xb[3 * bix + 1]; cz = xb[3 * bix + 2];
        if (t == 0) {
            float* sp = g_sub + (size_t)(b * MM + step) * 3;
            sp[0] = cx; sp[1] = cy; sp[2] = cz;
        }
    }
}

// ---------------- grid build (unchanged, proven) ------------------------------
__global__ void __launch_bounds__(512) build_grid_kernel(
    const float* __restrict__ src, int n, int G,
    float4* __restrict__ pts, int* __restrict__ pidx, int* __restrict__ cellstart)
{
    const int b = blockIdx.x;
    const int tid = threadIdx.x;
    const int G3 = G * G * G;
    const float fG = (float)G;
    const float* sp = (src ? src : (const float*)g_sub) + (size_t)b * n * 3;

    __shared__ int hist[512];
    __shared__ int cur[512];
    __shared__ int wsum[16];
    __shared__ short s_cid[8192];

    if (tid < G3) hist[tid] = 0;
    __syncthreads();

    for (int i = tid; i < n; i += 512) {
        const float* p = sp + 3 * i;
        int cx = min(G - 1, max(0, (int)(p[0] * fG)));
        int cy = min(G - 1, max(0, (int)(p[1] * fG)));
        int cz = min(G - 1, max(0, (int)(p[2] * fG)));
        int cid = (cz * G + cy) * G + cx;
        s_cid[i] = (short)cid;
        atomicAdd(&hist[cid], 1);
    }
    __syncthreads();

    int lane = tid & 31, wid = tid >> 5;
    int cnt = (tid < G3) ? hist[tid] : 0;
    int v = cnt;
#pragma unroll
    for (int o = 1; o < 32; o <<= 1) {
        int t2 = __shfl_up_sync(0xffffffffu, v, o);
        if (lane >= o) v += t2;
    }
    if (lane == 31) wsum[wid] = v;
    __syncthreads();
    if (tid == 0) {
        int acc = 0;
        for (int w = 0; w < 16; w++) { int t2 = wsum[w]; wsum[w] = acc; acc += t2; }
    }
    __syncthreads();
    int excl = v - cnt + wsum[wid];
    if (tid < G3) { cellstart[b * (G3 + 1) + tid] = excl; cur[tid] = excl; }
    if (tid == 0) cellstart[b * (G3 + 1) + G3] = n;
    __syncthreads();

    for (int i = tid; i < n; i += 512) {
        int cid = s_cid[i];
        int pos = atomicAdd(&cur[cid], 1);
        const float* p = sp + 3 * i;
        float x0 = p[0], y0 = p[1], z0 = p[2];
        pts[(size_t)b * n + pos] = make_float4(x0, y0, z0, x0 * x0 + y0 * y0 + z0 * z0);
        pidx[(size_t)b * n + pos] = i;
    }
}

// ---------------- KNN: warp/query, count-based termination, one final merge --
// Per ring: scan (R5-proven register insert) + cheap exact bound check:
// count of list entries <= bnd summed via redux.add; >= 16 <=> d16 <= bnd.
// Final merge runs ONCE per query (proven serial logic; p[] in smem, no LMEM).
template<int G, int NSRC>
__global__ void __launch_bounds__(256) knn_warp_kernel(
    const float4* __restrict__ pts, const int* __restrict__ pidx,
    const int* __restrict__ cellstart, int* __restrict__ outidx)
{
    constexpr int G3 = G * G * G;
    __shared__ float s_d[KK][256];
    __shared__ int   s_i[KK][256];
    __shared__ int   s_p[8][32];
    __shared__ int   s_res[8][KK];

    const int tid = threadIdx.x;
    const int lane = tid & 31;
    const int w = tid >> 5;
    const int b = blockIdx.y;
    const int j = blockIdx.x * 8 + w;          // gridded query slot; 250*8 = 2000 = MM
    const float fG = (float)G;

    float4 qp = g_pts2[(size_t)b * MM + j];
    const float qx = qp.x, qy = qp.y, qz = qp.z, qq = qp.w;
    const int cqx = min(G - 1, max(0, (int)(qx * fG)));
    const int cqy = min(G - 1, max(0, (int)(qy * fG)));
    const int cqz = min(G - 1, max(0, (int)(qz * fG)));

    const int* cs = cellstart + b * (G3 + 1);

    float dist[KK]; int idxr[KK];
#pragma unroll
    for (int r = 0; r < KK; r++) { dist[r] = 1e38f; idxr[r] = 0x7fffffff; }

    for (int R = 1; R <= G; R++) {
        // ---- scan ring R, lane-strided over its cells ----
        {
            int zlo = max(cqz - R, 0), zhi = min(cqz + R, G - 1);
            int ylo = max(cqy - R, 0), yhi = min(cqy + R, G - 1);
            int xlo = max(cqx - R, 0), xhi = min(cqx + R, G - 1);
            int c = 0;
            for (int cz = zlo; cz <= zhi; cz++)
                for (int cy = ylo; cy <= yhi; cy++)
                    for (int cx = xlo; cx <= xhi; cx++) {
                        if (R > 1) {
                            int ch = max(abs(cx - cqx), max(abs(cy - cqy), abs(cz - cqz)));
                            if (ch < R) continue;      // scanned in an earlier ring
                        }
                        if (((c++) & 31) != lane) continue;
                        int cid = (cz * G + cy) * G + cx;
                        int beg = cs[cid], end = cs[cid + 1];
                        for (int i2 = beg; i2 < end; i2++) {
                            float4 p = pts[(size_t)b * NSRC + i2];
                            int id = pidx[(size_t)b * NSRC + i2];
                            float t2 = qx * p.x;
                            t2 = fmaf(qy, p.y, t2);
                            t2 = fmaf(qz, p.z, t2);
                            float d = fmaf(-2.f, t2, qq + p.w);
                            if (d < dist[KK - 1] ||
                                (d == dist[KK - 1] && id < idxr[KK - 1])) {
                                dist[KK - 1] = d; idxr[KK - 1] = id;
#pragma unroll
                                for (int r = KK - 1; r > 0; --r) {
                                    bool sw = (dist[r] < dist[r - 1]) ||
                                              (dist[r] == dist[r - 1] && idxr[r] < idxr[r - 1]);
                                    if (sw) {
                                        float td = dist[r]; dist[r] = dist[r - 1]; dist[r - 1] = td;
                                        int ti = idxr[r]; idxr[r] = idxr[r - 1]; idxr[r - 1] = ti;
                                    }
                                }
                            }
                        }
                    }
        }
        // ---- exact termination check: warp-wide count of entries <= bnd ----
        float bnd = R * (1.0f / G);
        bnd = bnd * bnd * 0.9999f;
        unsigned cnt = 0;
#pragma unroll
        for (int r = 0; r < KK; r++) cnt += (dist[r] <= bnd) ? 1u : 0u;
        unsigned total = redux_add_u32(cnt);

        if (total >= (unsigned)KK || R >= G) {
            // ---- dump lists + one-shot serial merge (p[] in smem, no LMEM) ----
#pragma unroll
            for (int r = 0; r < KK; r++) {
                s_d[r][tid] = dist[r];
                s_i[r][tid] = idxr[r];
            }
            s_p[w][lane] = 0;
            __syncwarp();
            if (lane == 0) {
#pragma unroll 1
                for (int r = 0; r < KK; r++) {
                    float bd = 3e38f; int bi = 0x7fffffff; int bs = 0;
#pragma unroll
                    for (int ss = 0; ss < 32; ss++) {
                        int ps = s_p[w][ss];
                        if (ps < KK) {
                            float d = s_d[ps][w * 32 + ss];
                            int   ii = s_i[ps][w * 32 + ss];
                            if (d < bd || (d == bd && ii < bi)) { bd = d; bi = ii; bs = ss; }
                        }
                    }
                    s_p[w][bs]++;
                    s_res[w][r] = bi;
                }
            }
            __syncwarp();
            int q = g_pidx2[(size_t)b * MM + j];       // original query index
            if (lane < KK) {
                int ri = s_res[w][lane];
                ri = min(max(ri, 0), NSRC - 1);        // defensive clamp (no-op when correct)
                outidx[(size_t)(b * MM + q) * KK + lane] = ri;
            }
            break;
        }
    }
}

// ---------------- Layer 1 (unchanged, proven) ---------------------------------
__global__ void __launch_bounds__(128) layer1_kernel(const float* __restrict__ x,
                                                     const float* __restrict__ W1,
                                                     const float* __restrict__ b1) {
    __shared__ float sW[6 * C1W];
    int tid = threadIdx.x;
    for (int i = tid; i < 6 * C1W; i += 128) sW[i] = W1[i];
    __syncthreads();

    int warp = tid >> 5, lane = tid & 31;
    int b = blockIdx.y;
    int m = blockIdx.x * 4 + warp;

    const float* cp = g_sub + (size_t)(b * MM + m) * 3;
    float cx = cp[0], cy = cp[1], cz = cp[2];
    int c0 = lane * 4;
    float bb[4] = { b1[c0], b1[c0 + 1], b1[c0 + 2], b1[c0 + 3] };
    float best[4] = { 0.f, 0.f, 0.f, 0.f };
    const int* ip = g_idx1 + (size_t)(b * MM + m) * KK;

#pragma unroll 1
    for (int k = 0; k < KK; k++) {
        int n = ip[k];
        const float* np = x + ((size_t)b * NN + n) * 3;
        float nx = np[0], ny = np[1], nz = np[2];
        float f[6]; f[0] = nx - cx; f[1] = ny - cy; f[2] = nz - cz; f[3] = nx; f[4] = ny; f[5] = nz;
        float a[4] = { bb[0], bb[1], bb[2], bb[3] };
#pragma unroll
        for (int ff = 0; ff < 6; ff++) {
            const float* w2 = sW + ff * C1W + c0;
            a[0] += f[ff] * w2[0]; a[1] += f[ff] * w2[1];
            a[2] += f[ff] * w2[2]; a[3] += f[ff] * w2[3];
        }
#pragma unroll
        for (int e = 0; e < 4; e++) best[e] = fmaxf(best[e], fmaxf(a[e], 0.f));
    }
    *(float4*)(g_f1 + ((size_t)(b * MM + m) * C1W + c0)) =
        make_float4(best[0], best[1], best[2], best[3]);
}

// ---------------- Layer 2: FFMA2 (unchanged, proven) --------------------------
#define CH 4
__global__ void __launch_bounds__(256, 1) layer2_kernel(const float* __restrict__ b2) {
    __shared__ __align__(16) float sfeat[CH * 16 * 132];
    __shared__ int s_n[CH * 16];

    int b = blockIdx.y, m0 = blockIdx.x * CH;
    int tid = threadIdx.x;

    if (tid < CH * 16) {
        int mm = tid >> 4, k = tid & 15;
        int m = m0 + mm;
        int n = g_idx2[(size_t)(b * MM + m) * KK + k];
        s_n[tid] = n;
        const float* cp = g_sub + (size_t)(b * MM + m) * 3;
        const float* np = g_sub + (size_t)(b * MM + n) * 3;
        float* row = sfeat + tid * 132;
        row[128] = np[0] - cp[0];
        row[129] = np[1] - cp[1];
        row[130] = np[2] - cp[2];
        row[131] = 0.f;
    }
    __syncthreads();
    for (int t = tid; t < CH * 16 * 32; t += 256) {
        int p = t >> 5, fq = t & 31;
        int n = s_n[p];
        float4 v = *(const float4*)(g_f1 + (size_t)(b * MM + n) * C1W + fq * 4);
        *(float4*)(sfeat + p * 132 + fq * 4) = v;
    }
    int c = tid;
    u64 wpk[66];
#pragma unroll
    for (int qd = 0; qd < 33; qd++) {
        float4 w = g_W2q[qd * C2W + c];
        wpk[2 * qd]     = pack2(w.x, w.y);
        wpk[2 * qd + 1] = pack2(w.z, w.w);
    }
    u64 bias = (u64)__float_as_uint(b2[c]);
    __syncthreads();

    float best[CH];
#pragma unroll
    for (int mm = 0; mm < CH; mm++) best[mm] = 0.f;

#pragma unroll 1
    for (int k = 0; k < 16; k++) {
        u64 acc[CH];
#pragma unroll
        for (int mm = 0; mm < CH; mm++) acc[mm] = bias;
#pragma unroll
        for (int q2 = 0; q2 < 33; q2++) {
#pragma unroll
            for (int mm = 0; mm < CH; mm++) {
                const ulonglong2* vrow = (const ulonglong2*)(sfeat + (mm * 16 + k) * 132);
                ulonglong2 v = vrow[q2];
                acc[mm] = ffma2(v.x, wpk[2 * q2], acc[mm]);
                acc[mm] = ffma2(v.y, wpk[2 * q2 + 1], acc[mm]);
            }
        }
#pragma unroll
        for (int mm = 0; mm < CH; mm++) {
            float lo = __uint_as_float((unsigned)(acc[mm] & 0xffffffffu));
            float hi = __uint_as_float((unsigned)(acc[mm] >> 32));
            float a = lo + hi;
            best[mm] = fmaxf(best[mm], fmaxf(a, 0.f));
        }
    }
#pragma unroll
    for (int mm = 0; mm < CH; mm++)
        g_f2[(size_t)(b * MM + m0 + mm) * C2W + c] = best[mm];
}

// ---------------- pool (unchanged, proven) ------------------------------------
__global__ void __launch_bounds__(256) pool_kernel(float* __restrict__ out) {
    int c = threadIdx.x;
    int o = blockIdx.x;
    int b = blockIdx.y;
    const float* f = g_f2 + ((size_t)(b * MM + o * 20) * C2W) + c;
    float mx = -1e38f, sm = 0.f;
#pragma unroll
    for (int w = 0; w < 20; w++) {
        float v = f[(size_t)w * C2W];
        mx = fmaxf(mx, v);
        sm += v;
    }
    out[((size_t)b * C2W + c) * NOUT + o] = mx + sm / 20.0f;
}

// ---------------- launch ------------------------------------------------------
extern "C" void kernel_launch(void* const* d_in, const int* in_sizes, int n_in,
                              void* d_out, int out_size) {
    const float* x  = (const float*)d_in[0];
    const float* W1 = (const float*)d_in[1];
    const float* b1 = (const float*)d_in[2];
    const float* W2 = (const float*)d_in[3];
    const float* b2 = (const float*)d_in[4];
    float* out = (float*)d_out;

    float4* pts1; int* pidx1; int* strt1;
    float4* pts2; int* pidx2; int* strt2;
    int* idx1; int* idx2;
    cudaGetSymbolAddress((void**)&pts1, g_pts1);
    cudaGetSymbolAddress((void**)&pidx1, g_pidx1);
    cudaGetSymbolAddress((void**)&strt1, g_strt1);
    cudaGetSymbolAddress((void**)&pts2, g_pts2);
    cudaGetSymbolAddress((void**)&pidx2, g_pidx2);
    cudaGetSymbolAddress((void**)&strt2, g_strt2);
    cudaGetSymbolAddress((void**)&idx1, g_idx1);
    cudaGetSymbolAddress((void**)&idx2, g_idx2);

    w2prep_kernel<<<33, 256>>>(W2);                                  // 1st
    build_grid_kernel<<<BB, 512>>>(x, NN, G1, pts1, pidx1, strt1);   // 2nd
    filler_kernel<<<1, 256>>>();                                     // 3rd
    fps_kernel<<<BB, 512>>>(x);                                      // 4th <- profiled slot
    build_grid_kernel<<<BB, 512>>>(nullptr, MM, G2, pts2, pidx2, strt2);            // 5th
    knn_warp_kernel<G1, NN><<<dim3(MM / 8, BB), 256>>>(pts1, pidx1, strt1, idx1);   // 6th
    knn_warp_kernel<G2, MM><<<dim3(MM / 8, BB), 256>>>(pts2, pidx2, strt2, idx2);   // 7th
    layer1_kernel<<<dim3(MM / 4, BB), 128>>>(x, W1, b1);             // 8th
    layer2_kernel<<<dim3(MM / CH, BB), 256>>>(b2);                   // 9th
    pool_kernel<<<dim3(NOUT, BB), 256>>>(out);                       // 10th
}

// round 9
// speedup vs baseline: 2.3424x; 2.1560x over previous
#include <cuda_runtime.h>
#include <cstdint>

typedef unsigned long long u64;

// Problem constants
#define BB   8
#define NN   8192
#define MM   2000
#define KK   16
#define C1W  128
#define C2W  256
#define NOUT 100

#define G1   8          // grid for raw points  (cell 1/8)
#define G2   5          // grid for sub points  (cell 1/5)

// ---------------- scratch (device globals) ----------------------------------
__device__ float  g_sub [BB * MM * 3];
__device__ int    g_idx1[BB * MM * KK];
__device__ int    g_idx2[BB * MM * KK];
__device__ float  g_f1  [BB * MM * C1W];
__device__ float  g_f2  [BB * MM * C2W];
__device__ float4 g_W2q [33 * C2W];

__device__ float4 g_pts1 [BB * NN];
__device__ int    g_pidx1[BB * NN];
__device__ int    g_strt1[BB * (G1*G1*G1 + 1)];
__device__ float4 g_pts2 [BB * MM];
__device__ int    g_pidx2[BB * MM];
__device__ int    g_strt2[BB * (G2*G2*G2 + 1)];

__device__ __forceinline__ u64 ffma2(u64 a, u64 b, u64 c) {
    u64 d;
    asm("fma.rn.f32x2 %0, %1, %2, %3;" : "=l"(d) : "l"(a), "l"(b), "l"(c));
    return d;
}
__device__ __forceinline__ u64 fadd2(u64 a, u64 b) {
    u64 d;
    asm("add.rn.f32x2 %0, %1, %2;" : "=l"(d) : "l"(a), "l"(b));
    return d;
}
__device__ __forceinline__ u64 fmul2(u64 a, u64 b) {
    u64 d;
    asm("mul.rn.f32x2 %0, %1, %2;" : "=l"(d) : "l"(a), "l"(b));
    return d;
}
__device__ __forceinline__ void unpack2(u64 v, float& lo, float& hi) {
    asm("mov.b64 {%0, %1}, %2;" : "=f"(lo), "=f"(hi) : "l"(v));
}
__device__ __forceinline__ unsigned redux_max_u32(unsigned v) {
    unsigned r;
    asm("redux.sync.max.u32 %0, %1, 0xffffffff;" : "=r"(r) : "r"(v));
    return r;
}
__device__ __forceinline__ unsigned redux_min_u32(unsigned v) {
    unsigned r;
    asm("redux.sync.min.u32 %0, %1, 0xffffffff;" : "=r"(r) : "r"(v));
    return r;
}
__device__ __forceinline__ unsigned redux_add_u32(unsigned v) {
    unsigned r;
    asm("redux.sync.add.u32 %0, %1, 0xffffffff;" : "=r"(r) : "r"(v));
    return r;
}
__device__ __forceinline__ u64 pack2(float lo, float hi) {
    return ((u64)__float_as_uint(hi) << 32) | __float_as_uint(lo);
}

// ---------------- W2 prep ----------------------------------------------------
__global__ void w2prep_kernel(const float* __restrict__ W2) {
    int t = blockIdx.x * 256 + threadIdx.x;
    if (t >= 33 * C2W) return;
    int fq = t >> 8, c = t & 255;
    float v[4];
#pragma unroll
    for (int e = 0; e < 4; e++) {
        int fp = fq * 4 + e;
        float val = 0.f;
        if (fp < 131) {
            int r = (fp < 128) ? (fp + 3) : (fp - 128);
            val = W2[r * C2W + c];
        }
        v[e] = val;
    }
    g_W2q[t] = make_float4(v[0], v[1], v[2], v[3]);
}

// ---------------- FPS: 512 thr x 16 pts, f32x2-packed (R8, proven) ----------
__global__ void __launch_bounds__(512, 1) fps_kernel(const float* __restrict__ x) {
    const int b = blockIdx.x;
    const float* xb = x + (size_t)b * NN * 3;
    const int t = threadIdx.x;
    const int lane = t & 31, warp = t >> 5;       // 16 warps

    float mind[16];
    u64 px2[8], py2[8], pz2[8];
    {
        float pxs[16], pys[16], pzs[16];
#pragma unroll
        for (int j = 0; j < 16; j++) {
            int i = t + j * 512;
            pxs[j] = xb[3 * i]; pys[j] = xb[3 * i + 1]; pzs[j] = xb[3 * i + 2];
            mind[j] = 1e30f;
        }
#pragma unroll
        for (int jp = 0; jp < 8; jp++) {
            px2[jp] = pack2(pxs[jp], pxs[jp + 8]);
            py2[jp] = pack2(pys[jp], pys[jp + 8]);
            pz2[jp] = pack2(pzs[jp], pzs[jp + 8]);
        }
    }

    __shared__ unsigned s_val[2][32];
    __shared__ unsigned s_idx[2][32];
    if (t >= 16 && t < 32) {
        s_val[0][t] = 0u; s_val[1][t] = 0u;
        s_idx[0][t] = 0xffffffffu; s_idx[1][t] = 0xffffffffu;
    }
    if (t == 0) {
        float* sp = g_sub + (size_t)(b * MM) * 3;
        sp[0] = xb[0]; sp[1] = xb[1]; sp[2] = xb[2];
    }
    float cx = xb[0], cy = xb[1], cz = xb[2];
    __syncthreads();

    for (int step = 1; step < MM; step++) {
        u64 ncx2 = pack2(-cx, -cx), ncy2 = pack2(-cy, -cy), ncz2 = pack2(-cz, -cz);
        float bv = -1.0f;
#pragma unroll
        for (int jp = 0; jp < 8; jp++) {
            u64 dx2 = fadd2(px2[jp], ncx2);
            u64 dy2 = fadd2(py2[jp], ncy2);
            u64 dz2 = fadd2(pz2[jp], ncz2);
            u64 d2 = fmul2(dx2, dx2);
            d2 = ffma2(dy2, dy2, d2);
            d2 = ffma2(dz2, dz2, d2);
            float dlo, dhi; unpack2(d2, dlo, dhi);
            float m0 = fminf(mind[jp], dlo);
            float m1 = fminf(mind[jp + 8], dhi);
            mind[jp] = m0; mind[jp + 8] = m1;
            bv = fmaxf(bv, m0); bv = fmaxf(bv, m1);
        }
        unsigned cand = 0xffffffffu;
#pragma unroll
        for (int j = 15; j >= 0; j--)
            if (mind[j] == bv) cand = (unsigned)(t + j * 512);

        unsigned vb = __float_as_uint(bv);
        unsigned wmax = redux_max_u32(vb);
        unsigned widx = redux_min_u32(vb == wmax ? cand : 0xffffffffu);
        int buf = step & 1;
        if (lane == 0) { s_val[buf][warp] = wmax; s_idx[buf][warp] = widx; }
        __syncthreads();
        unsigned v2 = s_val[buf][lane];
        unsigned i2 = s_idx[buf][lane];
        unsigned bmax = redux_max_u32(v2);
        unsigned bix = redux_min_u32(v2 == bmax ? i2 : 0xffffffffu);

        cx = xb[3 * bix]; cy = xb[3 * bix + 1]; cz = xb[3 * bix + 2];
        if (t == 0) {
            float* sp = g_sub + (size_t)(b * MM + step) * 3;
            sp[0] = cx; sp[1] = cy; sp[2] = cz;
        }
    }
}

// ---------------- grid build (unchanged, proven) ------------------------------
__global__ void __launch_bounds__(512) build_grid_kernel(
    const float* __restrict__ src, int n, int G,
    float4* __restrict__ pts, int* __restrict__ pidx, int* __restrict__ cellstart)
{
    const int b = blockIdx.x;
    const int tid = threadIdx.x;
    const int G3 = G * G * G;
    const float fG = (float)G;
    const float* sp = (src ? src : (const float*)g_sub) + (size_t)b * n * 3;

    __shared__ int hist[512];
    __shared__ int cur[512];
    __shared__ int wsum[16];
    __shared__ short s_cid[8192];

    if (tid < G3) hist[tid] = 0;
    __syncthreads();

    for (int i = tid; i < n; i += 512) {
        const float* p = sp + 3 * i;
        int cx = min(G - 1, max(0, (int)(p[0] * fG)));
        int cy = min(G - 1, max(0, (int)(p[1] * fG)));
        int cz = min(G - 1, max(0, (int)(p[2] * fG)));
        int cid = (cz * G + cy) * G + cx;
        s_cid[i] = (short)cid;
        atomicAdd(&hist[cid], 1);
    }
    __syncthreads();

    int lane = tid & 31, wid = tid >> 5;
    int cnt = (tid < G3) ? hist[tid] : 0;
    int v = cnt;
#pragma unroll
    for (int o = 1; o < 32; o <<= 1) {
        int t2 = __shfl_up_sync(0xffffffffu, v, o);
        if (lane >= o) v += t2;
    }
    if (lane == 31) wsum[wid] = v;
    __syncthreads();
    if (tid == 0) {
        int acc = 0;
        for (int w = 0; w < 16; w++) { int t2 = wsum[w]; wsum[w] = acc; acc += t2; }
    }
    __syncthreads();
    int excl = v - cnt + wsum[wid];
    if (tid < G3) { cellstart[b * (G3 + 1) + tid] = excl; cur[tid] = excl; }
    if (tid == 0) cellstart[b * (G3 + 1) + G3] = n;
    __syncthreads();

    for (int i = tid; i < n; i += 512) {
        int cid = s_cid[i];
        int pos = atomicAdd(&cur[cid], 1);
        const float* p = sp + 3 * i;
        float x0 = p[0], y0 = p[1], z0 = p[2];
        pts[(size_t)b * n + pos] = make_float4(x0, y0, z0, x0 * x0 + y0 * y0 + z0 * z0);
        pidx[(size_t)b * n + pos] = i;
    }
}

// ---------------- KNN: warp/query, COALESCED segment scan --------------------
// A Chebyshev ring splits into contiguous cell-row segments (consecutive cx
// cells are adjacent in the sorted point array). The warp iterates segments
// uniformly; lanes stride candidates WITHIN each segment -> coalesced loads,
// balanced per-lane register top-16 lists. Termination + once-per-query merge
// are identical to the R8-proven code.
template<int G, int NSRC>
__global__ void __launch_bounds__(256) knn_warp_kernel(
    const float4* __restrict__ pts, const int* __restrict__ pidx,
    const int* __restrict__ cellstart, int* __restrict__ outidx)
{
    constexpr int G3 = G * G * G;
    __shared__ float s_d[KK][256];
    __shared__ int   s_i[KK][256];
    __shared__ int   s_p[8][32];
    __shared__ int   s_res[8][KK];

    const int tid = threadIdx.x;
    const int lane = tid & 31;
    const int w = tid >> 5;
    const int b = blockIdx.y;
    const int j = blockIdx.x * 8 + w;          // gridded query slot; 250*8 = 2000 = MM
    const float fG = (float)G;

    float4 qp = g_pts2[(size_t)b * MM + j];
    const float qx = qp.x, qy = qp.y, qz = qp.z, qq = qp.w;
    const int cqx = min(G - 1, max(0, (int)(qx * fG)));
    const int cqy = min(G - 1, max(0, (int)(qy * fG)));
    const int cqz = min(G - 1, max(0, (int)(qz * fG)));

    const int* cs = cellstart + b * (G3 + 1);
    const float4* ptsb = pts + (size_t)b * NSRC;
    const int* pidxb = pidx + (size_t)b * NSRC;

    float dist[KK]; int idxr[KK];
#pragma unroll
    for (int r = 0; r < KK; r++) { dist[r] = 1e38f; idxr[r] = 0x7fffffff; }

    for (int R = 1; R <= G; R++) {
        int zlo = max(cqz - R, 0), zhi = min(cqz + R, G - 1);
        int ylo = max(cqy - R, 0), yhi = min(cqy + R, G - 1);
        int xlo = max(cqx - R, 0), xhi = min(cqx + R, G - 1);
        for (int cz = zlo; cz <= zhi; cz++) {
            for (int cy = ylo; cy <= yhi; cy++) {
                // full row iff boundary plane of the ring (or R==1: whole box)
                bool full = (R == 1) || (cz - cqz == R) || (cqz - cz == R)
                                     || (cy - cqy == R) || (cqy - cy == R);
                int a0 = -1, b0 = -1, a1 = -1, b1 = -1;
                if (full) { a0 = xlo; b0 = xhi; }
                else {
                    if (cqx - R >= 0)     { a0 = cqx - R; b0 = a0; }
                    if (cqx + R <= G - 1) { a1 = cqx + R; b1 = a1; }
                }
                int rowbase = (cz * G + cy) * G;
#pragma unroll
                for (int sg = 0; sg < 2; sg++) {
                    int sa = sg == 0 ? a0 : a1;
                    int sb = sg == 0 ? b0 : b1;
                    if (sa < 0) continue;
                    int beg = cs[rowbase + sa];
                    int end = cs[rowbase + sb + 1];
                    for (int i2 = beg + lane; i2 < end; i2 += 32) {   // coalesced
                        float4 p = ptsb[i2];
                        int id = pidxb[i2];
                        float t2 = qx * p.x;
                        t2 = fmaf(qy, p.y, t2);
                        t2 = fmaf(qz, p.z, t2);
                        float d = fmaf(-2.f, t2, qq + p.w);
                        if (d < dist[KK - 1] ||
                            (d == dist[KK - 1] && id < idxr[KK - 1])) {
                            dist[KK - 1] = d; idxr[KK - 1] = id;
#pragma unroll
                            for (int r = KK - 1; r > 0; --r) {
                                bool sw = (dist[r] < dist[r - 1]) ||
                                          (dist[r] == dist[r - 1] && idxr[r] < idxr[r - 1]);
                                if (sw) {
                                    float td = dist[r]; dist[r] = dist[r - 1]; dist[r - 1] = td;
                                    int ti = idxr[r]; idxr[r] = idxr[r - 1]; idxr[r - 1] = ti;
                                }
                            }
                        }
                    }
                }
            }
        }
        // ---- exact termination: warp-wide count of entries <= bnd (R8) ----
        float bnd = R * (1.0f / G);
        bnd = bnd * bnd * 0.9999f;
        unsigned cnt = 0;
#pragma unroll
        for (int r = 0; r < KK; r++) cnt += (dist[r] <= bnd) ? 1u : 0u;
        unsigned total = redux_add_u32(cnt);

        if (total >= (unsigned)KK || R >= G) {
            // ---- dump lists + one-shot serial merge (R8-proven) ----
#pragma unroll
            for (int r = 0; r < KK; r++) {
                s_d[r][tid] = dist[r];
                s_i[r][tid] = idxr[r];
            }
            s_p[w][lane] = 0;
            __syncwarp();
            if (lane == 0) {
#pragma unroll 1
                for (int r = 0; r < KK; r++) {
                    float bd = 3e38f; int bi = 0x7fffffff; int bs = 0;
#pragma unroll
                    for (int ss = 0; ss < 32; ss++) {
                        int ps = s_p[w][ss];
                        if (ps < KK) {
                            float d = s_d[ps][w * 32 + ss];
                            int   ii = s_i[ps][w * 32 + ss];
                            if (d < bd || (d == bd && ii < bi)) { bd = d; bi = ii; bs = ss; }
                        }
                    }
                    s_p[w][bs]++;
                    s_res[w][r] = bi;
                }
            }
            __syncwarp();
            int q = g_pidx2[(size_t)b * MM + j];       // original query index
            if (lane < KK) {
                int ri = s_res[w][lane];
                ri = min(max(ri, 0), NSRC - 1);        // defensive clamp (no-op when correct)
                outidx[(size_t)(b * MM + q) * KK + lane] = ri;
            }
            break;
        }
    }
}

// ---------------- Layer 1 (unchanged, proven) ---------------------------------
__global__ void __launch_bounds__(128) layer1_kernel(const float* __restrict__ x,
                                                     const float* __restrict__ W1,
                                                     const float* __restrict__ b1) {
    __shared__ float sW[6 * C1W];
    int tid = threadIdx.x;
    for (int i = tid; i < 6 * C1W; i += 128) sW[i] = W1[i];
    __syncthreads();

    int warp = tid >> 5, lane = tid & 31;
    int b = blockIdx.y;
    int m = blockIdx.x * 4 + warp;

    const float* cp = g_sub + (size_t)(b * MM + m) * 3;
    float cx = cp[0], cy = cp[1], cz = cp[2];
    int c0 = lane * 4;
    float bb[4] = { b1[c0], b1[c0 + 1], b1[c0 + 2], b1[c0 + 3] };
    float best[4] = { 0.f, 0.f, 0.f, 0.f };
    const int* ip = g_idx1 + (size_t)(b * MM + m) * KK;

#pragma unroll 1
    for (int k = 0; k < KK; k++) {
        int n = ip[k];
        const float* np = x + ((size_t)b * NN + n) * 3;
        float nx = np[0], ny = np[1], nz = np[2];
        float f[6]; f[0] = nx - cx; f[1] = ny - cy; f[2] = nz - cz; f[3] = nx; f[4] = ny; f[5] = nz;
        float a[4] = { bb[0], bb[1], bb[2], bb[3] };
#pragma unroll
        for (int ff = 0; ff < 6; ff++) {
            const float* w2 = sW + ff * C1W + c0;
            a[0] += f[ff] * w2[0]; a[1] += f[ff] * w2[1];
            a[2] += f[ff] * w2[2]; a[3] += f[ff] * w2[3];
        }
#pragma unroll
        for (int e = 0; e < 4; e++) best[e] = fmaxf(best[e], fmaxf(a[e], 0.f));
    }
    *(float4*)(g_f1 + ((size_t)(b * MM + m) * C1W + c0)) =
        make_float4(best[0], best[1], best[2], best[3]);
}

// ---------------- Layer 2: FFMA2 (unchanged, proven) --------------------------
#define CH 4
__global__ void __launch_bounds__(256, 1) layer2_kernel(const float* __restrict__ b2) {
    __shared__ __align__(16) float sfeat[CH * 16 * 132];
    __shared__ int s_n[CH * 16];

    int b = blockIdx.y, m0 = blockIdx.x * CH;
    int tid = threadIdx.x;

    if (tid < CH * 16) {
        int mm = tid >> 4, k = tid & 15;
        int m = m0 + mm;
        int n = g_idx2[(size_t)(b * MM + m) * KK + k];
        s_n[tid] = n;
        const float* cp = g_sub + (size_t)(b * MM + m) * 3;
        const float* np = g_sub + (size_t)(b * MM + n) * 3;
        float* row = sfeat + tid * 132;
        row[128] = np[0] - cp[0];
        row[129] = np[1] - cp[1];
        row[130] = np[2] - cp[2];
        row[131] = 0.f;
    }
    __syncthreads();
    for (int t = tid; t < CH * 16 * 32; t += 256) {
        int p = t >> 5, fq = t & 31;
        int n = s_n[p];
        float4 v = *(const float4*)(g_f1 + (size_t)(b * MM + n) * C1W + fq * 4);
        *(float4*)(sfeat + p * 132 + fq * 4) = v;
    }
    int c = tid;
    u64 wpk[66];
#pragma unroll
    for (int qd = 0; qd < 33; qd++) {
        float4 w = g_W2q[qd * C2W + c];
        wpk[2 * qd]     = pack2(w.x, w.y);
        wpk[2 * qd + 1] = pack2(w.z, w.w);
    }
    u64 bias = (u64)__float_as_uint(b2[c]);
    __syncthreads();

    float best[CH];
#pragma unroll
    for (int mm = 0; mm < CH; mm++) best[mm] = 0.f;

#pragma unroll 1
    for (int k = 0; k < 16; k++) {
        u64 acc[CH];
#pragma unroll
        for (int mm = 0; mm < CH; mm++) acc[mm] = bias;
#pragma unroll
        for (int q2 = 0; q2 < 33; q2++) {
#pragma unroll
            for (int mm = 0; mm < CH; mm++) {
                const ulonglong2* vrow = (const ulonglong2*)(sfeat + (mm * 16 + k) * 132);
                ulonglong2 v = vrow[q2];
                acc[mm] = ffma2(v.x, wpk[2 * q2], acc[mm]);
                acc[mm] = ffma2(v.y, wpk[2 * q2 + 1], acc[mm]);
            }
        }
#pragma unroll
        for (int mm = 0; mm < CH; mm++) {
            float lo = __uint_as_float((unsigned)(acc[mm] & 0xffffffffu));
            float hi = __uint_as_float((unsigned)(acc[mm] >> 32));
            float a = lo + hi;
            best[mm] = fmaxf(best[mm], fmaxf(a, 0.f));
        }
    }
#pragma unroll
    for (int mm = 0; mm < CH; mm++)
        g_f2[(size_t)(b * MM + m0 + mm) * C2W + c] = best[mm];
}

// ---------------- pool (unchanged, proven) ------------------------------------
__global__ void __launch_bounds__(256) pool_kernel(float* __restrict__ out) {
    int c = threadIdx.x;
    int o = blockIdx.x;
    int b = blockIdx.y;
    const float* f = g_f2 + ((size_t)(b * MM + o * 20) * C2W) + c;
    float mx = -1e38f, sm = 0.f;
#pragma unroll
    for (int w = 0; w < 20; w++) {
        float v = f[(size_t)w * C2W];
        mx = fmaxf(mx, v);
        sm += v;
    }
    out[((size_t)b * C2W + c) * NOUT + o] = mx + sm / 20.0f;
}

// ---------------- launch ------------------------------------------------------
extern "C" void kernel_launch(void* const* d_in, const int* in_sizes, int n_in,
                              void* d_out, int out_size) {
    const float* x  = (const float*)d_in[0];
    const float* W1 = (const float*)d_in[1];
    const float* b1 = (const float*)d_in[2];
    const float* W2 = (const float*)d_in[3];
    const float* b2 = (const float*)d_in[4];
    float* out = (float*)d_out;

    float4* pts1; int* pidx1; int* strt1;
    float4* pts2; int* pidx2; int* strt2;
    int* idx1; int* idx2;
    cudaGetSymbolAddress((void**)&pts1, g_pts1);
    cudaGetSymbolAddress((void**)&pidx1, g_pidx1);
    cudaGetSymbolAddress((void**)&strt1, g_strt1);
    cudaGetSymbolAddress((void**)&pts2, g_pts2);
    cudaGetSymbolAddress((void**)&pidx2, g_pidx2);
    cudaGetSymbolAddress((void**)&strt2, g_strt2);
    cudaGetSymbolAddress((void**)&idx1, g_idx1);
    cudaGetSymbolAddress((void**)&idx2, g_idx2);

    fps_kernel<<<BB, 512>>>(x);                                      // 0
    build_grid_kernel<<<BB, 512>>>(x, NN, G1, pts1, pidx1, strt1);   // 1
    build_grid_kernel<<<BB, 512>>>(nullptr, MM, G2, pts2, pidx2, strt2);            // 2
    knn_warp_kernel<G1, NN><<<dim3(MM / 8, BB), 256>>>(pts1, pidx1, strt1, idx1);   // 3 <- profiled
    knn_warp_kernel<G2, MM><<<dim3(MM / 8, BB), 256>>>(pts2, pidx2, strt2, idx2);   // 4
    w2prep_kernel<<<33, 256>>>(W2);                                  // 5
    layer1_kernel<<<dim3(MM / 4, BB), 128>>>(x, W1, b1);             // 6
    layer2_kernel<<<dim3(MM / CH, BB), 256>>>(b2);                   // 7
    pool_kernel<<<dim3(NOUT, BB), 256>>>(out);                       // 8
}

// round 10
// speedup vs baseline: 2.7972x; 1.1942x over previous
#include <cuda_runtime.h>
#include <cstdint>

typedef unsigned long long u64;

// Problem constants
#define BB   8
#define NN   8192
#define MM   2000
#define KK   16
#define C1W  128
#define C2W  256
#define NOUT 100

#define G1   8          // grid for raw points  (cell 1/8)
#define G2   5          // grid for sub points  (cell 1/5)

// ---------------- scratch (device globals) ----------------------------------
__device__ float  g_sub [BB * MM * 3];
__device__ int    g_idx1[BB * MM * KK];
__device__ int    g_idx2[BB * MM * KK];
__device__ float  g_f1  [BB * MM * C1W];
__device__ float  g_f2  [BB * MM * C2W];
__device__ float4 g_W2q [33 * C2W];

__device__ float4 g_pts1 [BB * NN];
__device__ int    g_pidx1[BB * NN];
__device__ int    g_strt1[BB * (G1*G1*G1 + 1)];
__device__ float4 g_pts2 [BB * MM];
__device__ int    g_pidx2[BB * MM];
__device__ int    g_strt2[BB * (G2*G2*G2 + 1)];

__device__ __forceinline__ u64 ffma2(u64 a, u64 b, u64 c) {
    u64 d;
    asm("fma.rn.f32x2 %0, %1, %2, %3;" : "=l"(d) : "l"(a), "l"(b), "l"(c));
    return d;
}
__device__ __forceinline__ u64 fadd2(u64 a, u64 b) {
    u64 d;
    asm("add.rn.f32x2 %0, %1, %2;" : "=l"(d) : "l"(a), "l"(b));
    return d;
}
__device__ __forceinline__ u64 fmul2(u64 a, u64 b) {
    u64 d;
    asm("mul.rn.f32x2 %0, %1, %2;" : "=l"(d) : "l"(a), "l"(b));
    return d;
}
__device__ __forceinline__ void unpack2(u64 v, float& lo, float& hi) {
    asm("mov.b64 {%0, %1}, %2;" : "=f"(lo), "=f"(hi) : "l"(v));
}
__device__ __forceinline__ unsigned redux_max_u32(unsigned v) {
    unsigned r;
    asm("redux.sync.max.u32 %0, %1, 0xffffffff;" : "=r"(r) : "r"(v));
    return r;
}
__device__ __forceinline__ unsigned redux_min_u32(unsigned v) {
    unsigned r;
    asm("redux.sync.min.u32 %0, %1, 0xffffffff;" : "=r"(r) : "r"(v));
    return r;
}
__device__ __forceinline__ unsigned redux_add_u32(unsigned v) {
    unsigned r;
    asm("redux.sync.add.u32 %0, %1, 0xffffffff;" : "=r"(r) : "r"(v));
    return r;
}
__device__ __forceinline__ u64 pack2(float lo, float hi) {
    return ((u64)__float_as_uint(hi) << 32) | __float_as_uint(lo);
}
// order-preserving float->u32 (handles negatives); used ONLY for merge ordering
__device__ __forceinline__ unsigned fkey(float f) {
    unsigned u = __float_as_uint(f);
    return u ^ (((int)u >> 31) | 0x80000000u);
}

// ---------------- W2 prep ----------------------------------------------------
__global__ void w2prep_kernel(const float* __restrict__ W2) {
    int t = blockIdx.x * 256 + threadIdx.x;
    if (t >= 33 * C2W) return;
    int fq = t >> 8, c = t & 255;
    float v[4];
#pragma unroll
    for (int e = 0; e < 4; e++) {
        int fp = fq * 4 + e;
        float val = 0.f;
        if (fp < 131) {
            int r = (fp < 128) ? (fp + 3) : (fp - 128);
            val = W2[r * C2W + c];
        }
        v[e] = val;
    }
    g_W2q[t] = make_float4(v[0], v[1], v[2], v[3]);
}

// ---------------- FPS: 512 thr x 16 pts, f32x2-packed (R8, proven) ----------
__global__ void __launch_bounds__(512, 1) fps_kernel(const float* __restrict__ x) {
    const int b = blockIdx.x;
    const float* xb = x + (size_t)b * NN * 3;
    const int t = threadIdx.x;
    const int lane = t & 31, warp = t >> 5;       // 16 warps

    float mind[16];
    u64 px2[8], py2[8], pz2[8];
    {
        float pxs[16], pys[16], pzs[16];
#pragma unroll
        for (int j = 0; j < 16; j++) {
            int i = t + j * 512;
            pxs[j] = xb[3 * i]; pys[j] = xb[3 * i + 1]; pzs[j] = xb[3 * i + 2];
            mind[j] = 1e30f;
        }
#pragma unroll
        for (int jp = 0; jp < 8; jp++) {
            px2[jp] = pack2(pxs[jp], pxs[jp + 8]);
            py2[jp] = pack2(pys[jp], pys[jp + 8]);
            pz2[jp] = pack2(pzs[jp], pzs[jp + 8]);
        }
    }

    __shared__ unsigned s_val[2][32];
    __shared__ unsigned s_idx[2][32];
    if (t >= 16 && t < 32) {
        s_val[0][t] = 0u; s_val[1][t] = 0u;
        s_idx[0][t] = 0xffffffffu; s_idx[1][t] = 0xffffffffu;
    }
    if (t == 0) {
        float* sp = g_sub + (size_t)(b * MM) * 3;
        sp[0] = xb[0]; sp[1] = xb[1]; sp[2] = xb[2];
    }
    float cx = xb[0], cy = xb[1], cz = xb[2];
    __syncthreads();

    for (int step = 1; step < MM; step++) {
        u64 ncx2 = pack2(-cx, -cx), ncy2 = pack2(-cy, -cy), ncz2 = pack2(-cz, -cz);
        float bv = -1.0f;
#pragma unroll
        for (int jp = 0; jp < 8; jp++) {
            u64 dx2 = fadd2(px2[jp], ncx2);
            u64 dy2 = fadd2(py2[jp], ncy2);
            u64 dz2 = fadd2(pz2[jp], ncz2);
            u64 d2 = fmul2(dx2, dx2);
            d2 = ffma2(dy2, dy2, d2);
            d2 = ffma2(dz2, dz2, d2);
            float dlo, dhi; unpack2(d2, dlo, dhi);
            float m0 = fminf(mind[jp], dlo);
            float m1 = fminf(mind[jp + 8], dhi);
            mind[jp] = m0; mind[jp + 8] = m1;
            bv = fmaxf(bv, m0); bv = fmaxf(bv, m1);
        }
        unsigned cand = 0xffffffffu;
#pragma unroll
        for (int j = 15; j >= 0; j--)
            if (mind[j] == bv) cand = (unsigned)(t + j * 512);

        unsigned vb = __float_as_uint(bv);
        unsigned wmax = redux_max_u32(vb);
        unsigned widx = redux_min_u32(vb == wmax ? cand : 0xffffffffu);
        int buf = step & 1;
        if (lane == 0) { s_val[buf][warp] = wmax; s_idx[buf][warp] = widx; }
        __syncthreads();
        unsigned v2 = s_val[buf][lane];
        unsigned i2 = s_idx[buf][lane];
        unsigned bmax = redux_max_u32(v2);
        unsigned bix = redux_min_u32(v2 == bmax ? i2 : 0xffffffffu);

        cx = xb[3 * bix]; cy = xb[3 * bix + 1]; cz = xb[3 * bix + 2];
        if (t == 0) {
            float* sp = g_sub + (size_t)(b * MM + step) * 3;
            sp[0] = cx; sp[1] = cy; sp[2] = cz;
        }
    }
}

// ---------------- grid build (unchanged, proven) ------------------------------
__global__ void __launch_bounds__(512) build_grid_kernel(
    const float* __restrict__ src, int n, int G,
    float4* __restrict__ pts, int* __restrict__ pidx, int* __restrict__ cellstart)
{
    const int b = blockIdx.x;
    const int tid = threadIdx.x;
    const int G3 = G * G * G;
    const float fG = (float)G;
    const float* sp = (src ? src : (const float*)g_sub) + (size_t)b * n * 3;

    __shared__ int hist[512];
    __shared__ int cur[512];
    __shared__ int wsum[16];
    __shared__ short s_cid[8192];

    if (tid < G3) hist[tid] = 0;
    __syncthreads();

    for (int i = tid; i < n; i += 512) {
        const float* p = sp + 3 * i;
        int cx = min(G - 1, max(0, (int)(p[0] * fG)));
        int cy = min(G - 1, max(0, (int)(p[1] * fG)));
        int cz = min(G - 1, max(0, (int)(p[2] * fG)));
        int cid = (cz * G + cy) * G + cx;
        s_cid[i] = (short)cid;
        atomicAdd(&hist[cid], 1);
    }
    __syncthreads();

    int lane = tid & 31, wid = tid >> 5;
    int cnt = (tid < G3) ? hist[tid] : 0;
    int v = cnt;
#pragma unroll
    for (int o = 1; o < 32; o <<= 1) {
        int t2 = __shfl_up_sync(0xffffffffu, v, o);
        if (lane >= o) v += t2;
    }
    if (lane == 31) wsum[wid] = v;
    __syncthreads();
    if (tid == 0) {
        int acc = 0;
        for (int w = 0; w < 16; w++) { int t2 = wsum[w]; wsum[w] = acc; acc += t2; }
    }
    __syncthreads();
    int excl = v - cnt + wsum[wid];
    if (tid < G3) { cellstart[b * (G3 + 1) + tid] = excl; cur[tid] = excl; }
    if (tid == 0) cellstart[b * (G3 + 1) + G3] = n;
    __syncthreads();

    for (int i = tid; i < n; i += 512) {
        int cid = s_cid[i];
        int pos = atomicAdd(&cur[cid], 1);
        const float* p = sp + 3 * i;
        float x0 = p[0], y0 = p[1], z0 = p[2];
        pts[(size_t)b * n + pos] = make_float4(x0, y0, z0, x0 * x0 + y0 * y0 + z0 * z0);
        pidx[(size_t)b * n + pos] = i;
    }
}

// ---------------- KNN: warp/query, coalesced segments, PARALLEL redux merge --
// Scan + termination identical to R9 (proven, exact). Final merge replaced by
// a 16-round all-lane pop: redux.min on order-preserving key, then redux.min
// on tied index. ids are globally unique across lanes (disjoint partitions),
// so exactly one lane pops per round -> output provably identical to the
// serial merge. Sentinel pops can only happen with <16 real entries, which
// the termination condition excludes.
template<int G, int NSRC>
__global__ void __launch_bounds__(256) knn_warp_kernel(
    const float4* __restrict__ pts, const int* __restrict__ pidx,
    const int* __restrict__ cellstart, int* __restrict__ outidx)
{
    constexpr int G3 = G * G * G;
    __shared__ float s_d[KK][256];
    __shared__ int   s_i[KK][256];

    const int tid = threadIdx.x;
    const int lane = tid & 31;
    const int w = tid >> 5;
    const int b = blockIdx.y;
    const int j = blockIdx.x * 8 + w;          // gridded query slot; 250*8 = 2000 = MM
    const float fG = (float)G;

    float4 qp = g_pts2[(size_t)b * MM + j];
    const float qx = qp.x, qy = qp.y, qz = qp.z, qq = qp.w;
    const int cqx = min(G - 1, max(0, (int)(qx * fG)));
    const int cqy = min(G - 1, max(0, (int)(qy * fG)));
    const int cqz = min(G - 1, max(0, (int)(qz * fG)));

    const int* cs = cellstart + b * (G3 + 1);
    const float4* ptsb = pts + (size_t)b * NSRC;
    const int* pidxb = pidx + (size_t)b * NSRC;

    float dist[KK]; int idxr[KK];
#pragma unroll
    for (int r = 0; r < KK; r++) { dist[r] = 1e38f; idxr[r] = 0x7fffffff; }

    for (int R = 1; R <= G; R++) {
        int zlo = max(cqz - R, 0), zhi = min(cqz + R, G - 1);
        int ylo = max(cqy - R, 0), yhi = min(cqy + R, G - 1);
        int xlo = max(cqx - R, 0), xhi = min(cqx + R, G - 1);
        for (int cz = zlo; cz <= zhi; cz++) {
            for (int cy = ylo; cy <= yhi; cy++) {
                // full row iff boundary plane of the ring (or R==1: whole box)
                bool full = (R == 1) || (cz - cqz == R) || (cqz - cz == R)
                                     || (cy - cqy == R) || (cqy - cy == R);
                int a0 = -1, b0 = -1, a1 = -1, b1 = -1;
                if (full) { a0 = xlo; b0 = xhi; }
                else {
                    if (cqx - R >= 0)     { a0 = cqx - R; b0 = a0; }
                    if (cqx + R <= G - 1) { a1 = cqx + R; b1 = a1; }
                }
                int rowbase = (cz * G + cy) * G;
#pragma unroll
                for (int sg = 0; sg < 2; sg++) {
                    int sa = sg == 0 ? a0 : a1;
                    int sb = sg == 0 ? b0 : b1;
                    if (sa < 0) continue;
                    int beg = cs[rowbase + sa];
                    int end = cs[rowbase + sb + 1];
                    for (int i2 = beg + lane; i2 < end; i2 += 32) {   // coalesced
                        float4 p = ptsb[i2];
                        int id = pidxb[i2];
                        float t2 = qx * p.x;
                        t2 = fmaf(qy, p.y, t2);
                        t2 = fmaf(qz, p.z, t2);
                        float d = fmaf(-2.f, t2, qq + p.w);
                        if (d < dist[KK - 1] ||
                            (d == dist[KK - 1] && id < idxr[KK - 1])) {
                            dist[KK - 1] = d; idxr[KK - 1] = id;
#pragma unroll
                            for (int r = KK - 1; r > 0; --r) {
                                bool sw = (dist[r] < dist[r - 1]) ||
                                          (dist[r] == dist[r - 1] && idxr[r] < idxr[r - 1]);
                                if (sw) {
                                    float td = dist[r]; dist[r] = dist[r - 1]; dist[r - 1] = td;
                                    int ti = idxr[r]; idxr[r] = idxr[r - 1]; idxr[r - 1] = ti;
                                }
                            }
                        }
                    }
                }
            }
        }
        // ---- exact termination: warp-wide count of entries <= bnd (R8) ----
        float bnd = R * (1.0f / G);
        bnd = bnd * bnd * 0.9999f;
        unsigned cnt = 0;
#pragma unroll
        for (int r = 0; r < KK; r++) cnt += (dist[r] <= bnd) ? 1u : 0u;
        unsigned total = redux_add_u32(cnt);

        if (total >= (unsigned)KK || R >= G) {
            // ---- dump lists, then parallel 16-round pop merge ----
#pragma unroll
            for (int r = 0; r < KK; r++) {
                s_d[r][tid] = dist[r];
                s_i[r][tid] = idxr[r];
            }
            __syncwarp();
            int p = 0;
            float hd = dist[0]; int hid = idxr[0];
            int resi = 0x7fffffff;
#pragma unroll 1
            for (int r = 0; r < KK; r++) {
                unsigned k = fkey(hd);
                unsigned m = redux_min_u32(k);
                unsigned wi = redux_min_u32(k == m ? (unsigned)hid : 0xffffffffu);
                if (lane == r) resi = (int)wi;
                if (k == m && (unsigned)hid == wi) {
                    p++;
                    if (p < KK) { hd = s_d[p][tid]; hid = s_i[p][tid]; }
                    else        { hd = 3e38f; hid = 0x7fffffff; }
                }
            }
            int q = g_pidx2[(size_t)b * MM + j];       // original query index
            if (lane < KK) {
                int ri = min(max(resi, 0), NSRC - 1);  // defensive clamp (no-op when correct)
                outidx[(size_t)(b * MM + q) * KK + lane] = ri;
            }
            break;
        }
    }
}

// ---------------- Layer 1 (unchanged, proven) ---------------------------------
__global__ void __launch_bounds__(128) layer1_kernel(const float* __restrict__ x,
                                                     const float* __restrict__ W1,
                                                     const float* __restrict__ b1) {
    __shared__ float sW[6 * C1W];
    int tid = threadIdx.x;
    for (int i = tid; i < 6 * C1W; i += 128) sW[i] = W1[i];
    __syncthreads();

    int warp = tid >> 5, lane = tid & 31;
    int b = blockIdx.y;
    int m = blockIdx.x * 4 + warp;

    const float* cp = g_sub + (size_t)(b * MM + m) * 3;
    float cx = cp[0], cy = cp[1], cz = cp[2];
    int c0 = lane * 4;
    float bb[4] = { b1[c0], b1[c0 + 1], b1[c0 + 2], b1[c0 + 3] };
    float best[4] = { 0.f, 0.f, 0.f, 0.f };
    const int* ip = g_idx1 + (size_t)(b * MM + m) * KK;

#pragma unroll 1
    for (int k = 0; k < KK; k++) {
        int n = ip[k];
        const float* np = x + ((size_t)b * NN + n) * 3;
        float nx = np[0], ny = np[1], nz = np[2];
        float f[6]; f[0] = nx - cx; f[1] = ny - cy; f[2] = nz - cz; f[3] = nx; f[4] = ny; f[5] = nz;
        float a[4] = { bb[0], bb[1], bb[2], bb[3] };
#pragma unroll
        for (int ff = 0; ff < 6; ff++) {
            const float* w2 = sW + ff * C1W + c0;
            a[0] += f[ff] * w2[0]; a[1] += f[ff] * w2[1];
            a[2] += f[ff] * w2[2]; a[3] += f[ff] * w2[3];
        }
#pragma unroll
        for (int e = 0; e < 4; e++) best[e] = fmaxf(best[e], fmaxf(a[e], 0.f));
    }
    *(float4*)(g_f1 + ((size_t)(b * MM + m) * C1W + c0)) =
        make_float4(best[0], best[1], best[2], best[3]);
}

// ---------------- Layer 2: FFMA2 (unchanged, proven) --------------------------
#define CH 4
__global__ void __launch_bounds__(256, 1) layer2_kernel(const float* __restrict__ b2) {
    __shared__ __align__(16) float sfeat[CH * 16 * 132];
    __shared__ int s_n[CH * 16];

    int b = blockIdx.y, m0 = blockIdx.x * CH;
    int tid = threadIdx.x;

    if (tid < CH * 16) {
        int mm = tid >> 4, k = tid & 15;
        int m = m0 + mm;
        int n = g_idx2[(size_t)(b * MM + m) * KK + k];
        s_n[tid] = n;
        const float* cp = g_sub + (size_t)(b * MM + m) * 3;
        const float* np = g_sub + (size_t)(b * MM + n) * 3;
        float* row = sfeat + tid * 132;
        row[128] = np[0] - cp[0];
        row[129] = np[1] - cp[1];
        row[130] = np[2] - cp[2];
        row[131] = 0.f;
    }
    __syncthreads();
    for (int t = tid; t < CH * 16 * 32; t += 256) {
        int p = t >> 5, fq = t & 31;
        int n = s_n[p];
        float4 v = *(const float4*)(g_f1 + (size_t)(b * MM + n) * C1W + fq * 4);
        *(float4*)(sfeat + p * 132 + fq * 4) = v;
    }
    int c = tid;
    u64 wpk[66];
#pragma unroll
    for (int qd = 0; qd < 33; qd++) {
        float4 w = g_W2q[qd * C2W + c];
        wpk[2 * qd]     = pack2(w.x, w.y);
        wpk[2 * qd + 1] = pack2(w.z, w.w);
    }
    u64 bias = (u64)__float_as_uint(b2[c]);
    __syncthreads();

    float best[CH];
#pragma unroll
    for (int mm = 0; mm < CH; mm++) best[mm] = 0.f;

#pragma unroll 1
    for (int k = 0; k < 16; k++) {
        u64 acc[CH];
#pragma unroll
        for (int mm = 0; mm < CH; mm++) acc[mm] = bias;
#pragma unroll
        for (int q2 = 0; q2 < 33; q2++) {
#pragma unroll
            for (int mm = 0; mm < CH; mm++) {
                const ulonglong2* vrow = (const ulonglong2*)(sfeat + (mm * 16 + k) * 132);
                ulonglong2 v = vrow[q2];
                acc[mm] = ffma2(v.x, wpk[2 * q2], acc[mm]);
                acc[mm] = ffma2(v.y, wpk[2 * q2 + 1], acc[mm]);
            }
        }
#pragma unroll
        for (int mm = 0; mm < CH; mm++) {
            float lo = __uint_as_float((unsigned)(acc[mm] & 0xffffffffu));
            float hi = __uint_as_float((unsigned)(acc[mm] >> 32));
            float a = lo + hi;
            best[mm] = fmaxf(best[mm], fmaxf(a, 0.f));
        }
    }
#pragma unroll
    for (int mm = 0; mm < CH; mm++)
        g_f2[(size_t)(b * MM + m0 + mm) * C2W + c] = best[mm];
}

// ---------------- pool (unchanged, proven) ------------------------------------
__global__ void __launch_bounds__(256) pool_kernel(float* __restrict__ out) {
    int c = threadIdx.x;
    int o = blockIdx.x;
    int b = blockIdx.y;
    const float* f = g_f2 + ((size_t)(b * MM + o * 20) * C2W) + c;
    float mx = -1e38f, sm = 0.f;
#pragma unroll
    for (int w = 0; w < 20; w++) {
        float v = f[(size_t)w * C2W];
        mx = fmaxf(mx, v);
        sm += v;
    }
    out[((size_t)b * C2W + c) * NOUT + o] = mx + sm / 20.0f;
}

// ---------------- launch ------------------------------------------------------
extern "C" void kernel_launch(void* const* d_in, const int* in_sizes, int n_in,
                              void* d_out, int out_size) {
    const float* x  = (const float*)d_in[0];
    const float* W1 = (const float*)d_in[1];
    const float* b1 = (const float*)d_in[2];
    const float* W2 = (const float*)d_in[3];
    const float* b2 = (const float*)d_in[4];
    float* out = (float*)d_out;

    float4* pts1; int* pidx1; int* strt1;
    float4* pts2; int* pidx2; int* strt2;
    int* idx1; int* idx2;
    cudaGetSymbolAddress((void**)&pts1, g_pts1);
    cudaGetSymbolAddress((void**)&pidx1, g_pidx1);
    cudaGetSymbolAddress((void**)&strt1, g_strt1);
    cudaGetSymbolAddress((void**)&pts2, g_pts2);
    cudaGetSymbolAddress((void**)&pidx2, g_pidx2);
    cudaGetSymbolAddress((void**)&strt2, g_strt2);
    cudaGetSymbolAddress((void**)&idx1, g_idx1);
    cudaGetSymbolAddress((void**)&idx2, g_idx2);

    fps_kernel<<<BB, 512>>>(x);                                      // 0
    build_grid_kernel<<<BB, 512>>>(x, NN, G1, pts1, pidx1, strt1);   // 1
    build_grid_kernel<<<BB, 512>>>(nullptr, MM, G2, pts2, pidx2, strt2);            // 2
    knn_warp_kernel<G2, MM><<<dim3(MM / 8, BB), 256>>>(pts2, pidx2, strt2, idx2);   // 3 <- profiled
    knn_warp_kernel<G1, NN><<<dim3(MM / 8, BB), 256>>>(pts1, pidx1, strt1, idx1);   // 4
    w2prep_kernel<<<33, 256>>>(W2);                                  // 5
    layer1_kernel<<<dim3(MM / 4, BB), 128>>>(x, W1, b1);             // 6
    layer2_kernel<<<dim3(MM / CH, BB), 256>>>(b2);                   // 7
    pool_kernel<<<dim3(NOUT, BB), 256>>>(out);                       // 8
}

// round 11
// speedup vs baseline: 2.9294x; 1.0472x over previous
#include <cuda_runtime.h>
#include <cstdint>

typedef unsigned long long u64;

// Problem constants
#define BB   8
#define NN   8192
#define MM   2000
#define KK   16
#define C1W  128
#define C2W  256
#define NOUT 100

#define G1   8          // grid for raw points  (cell 1/8)
#define G2   5          // grid for sub points  (cell 1/5)

// ---------------- scratch (device globals) ----------------------------------
__device__ float  g_sub [BB * MM * 3];
__device__ int    g_idx1[BB * MM * KK];
__device__ int    g_idx2[BB * MM * KK];
__device__ float  g_f1  [BB * MM * C1W];
__device__ float  g_f2  [BB * MM * C2W];
__device__ float4 g_W2q [33 * C2W];

__device__ float4 g_pts1 [BB * NN];
__device__ int    g_pidx1[BB * NN];
__device__ int    g_strt1[BB * (G1*G1*G1 + 1)];
__device__ float4 g_pts2 [BB * MM];
__device__ int    g_pidx2[BB * MM];
__device__ int    g_strt2[BB * (G2*G2*G2 + 1)];

__device__ __forceinline__ u64 ffma2(u64 a, u64 b, u64 c) {
    u64 d;
    asm("fma.rn.f32x2 %0, %1, %2, %3;" : "=l"(d) : "l"(a), "l"(b), "l"(c));
    return d;
}
__device__ __forceinline__ u64 fadd2(u64 a, u64 b) {
    u64 d;
    asm("add.rn.f32x2 %0, %1, %2;" : "=l"(d) : "l"(a), "l"(b));
    return d;
}
__device__ __forceinline__ u64 fmul2(u64 a, u64 b) {
    u64 d;
    asm("mul.rn.f32x2 %0, %1, %2;" : "=l"(d) : "l"(a), "l"(b));
    return d;
}
__device__ __forceinline__ void unpack2(u64 v, float& lo, float& hi) {
    asm("mov.b64 {%0, %1}, %2;" : "=f"(lo), "=f"(hi) : "l"(v));
}
__device__ __forceinline__ unsigned redux_max_u32(unsigned v) {
    unsigned r;
    asm("redux.sync.max.u32 %0, %1, 0xffffffff;" : "=r"(r) : "r"(v));
    return r;
}
__device__ __forceinline__ unsigned redux_min_u32(unsigned v) {
    unsigned r;
    asm("redux.sync.min.u32 %0, %1, 0xffffffff;" : "=r"(r) : "r"(v));
    return r;
}
__device__ __forceinline__ unsigned redux_add_u32(unsigned v) {
    unsigned r;
    asm("redux.sync.add.u32 %0, %1, 0xffffffff;" : "=r"(r) : "r"(v));
    return r;
}
__device__ __forceinline__ u64 pack2(float lo, float hi) {
    return ((u64)__float_as_uint(hi) << 32) | __float_as_uint(lo);
}
// order-preserving float->u32 (handles negatives); used ONLY for merge ordering
__device__ __forceinline__ unsigned fkey(float f) {
    unsigned u = __float_as_uint(f);
    return u ^ (((int)u >> 31) | 0x80000000u);
}

// ---------------- W2 prep ----------------------------------------------------
__global__ void w2prep_kernel(const float* __restrict__ W2) {
    int t = blockIdx.x * 256 + threadIdx.x;
    if (t >= 33 * C2W) return;
    int fq = t >> 8, c = t & 255;
    float v[4];
#pragma unroll
    for (int e = 0; e < 4; e++) {
        int fp = fq * 4 + e;
        float val = 0.f;
        if (fp < 131) {
            int r = (fp < 128) ? (fp + 3) : (fp - 128);
            val = W2[r * C2W + c];
        }
        v[e] = val;
    }
    g_W2q[t] = make_float4(v[0], v[1], v[2], v[3]);
}

// ---------------- filler (pads launch index so fps lands at profiled slot 3)
__global__ void filler_kernel() {
    if (blockIdx.x == 0) g_f2[threadIdx.x] = 0.f;   // overwritten by layer2 later
}

// ---------------- FPS: value-only reduction + winner-only argmin index ------
// Distance update math is bit-identical to the R8-proven version. bv is a
// tree max (associative => same value as linear). Warp redux.max -> smem ->
// block redux.max gives bmax; only threads with bv == bmax (the global-max
// owners, ~1 per block) scan their 16 minds for the first matching index and
// atomicMin it into a double-buffered smem slot. Winner set and min-index
// selection identical to the previous two-level (max,min-idx) reduction.
__global__ void __launch_bounds__(512, 1) fps_kernel(const float* __restrict__ x) {
    const int b = blockIdx.x;
    const float* xb = x + (size_t)b * NN * 3;
    const int t = threadIdx.x;
    const int lane = t & 31, warp = t >> 5;       // 16 warps

    float mind[16];
    u64 px2[8], py2[8], pz2[8];
    {
        float pxs[16], pys[16], pzs[16];
#pragma unroll
        for (int j = 0; j < 16; j++) {
            int i = t + j * 512;
            pxs[j] = xb[3 * i]; pys[j] = xb[3 * i + 1]; pzs[j] = xb[3 * i + 2];
            mind[j] = 1e30f;
        }
#pragma unroll
        for (int jp = 0; jp < 8; jp++) {
            px2[jp] = pack2(pxs[jp], pxs[jp + 8]);
            py2[jp] = pack2(pys[jp], pys[jp + 8]);
            pz2[jp] = pack2(pzs[jp], pzs[jp + 8]);
        }
    }

    __shared__ unsigned s_val[2][32];
    __shared__ unsigned s_win[2];
    if (t >= 16 && t < 32) { s_val[0][t] = 0u; s_val[1][t] = 0u; }
    if (t == 0) {
        s_win[0] = 0xffffffffu; s_win[1] = 0xffffffffu;
        float* sp = g_sub + (size_t)(b * MM) * 3;
        sp[0] = xb[0]; sp[1] = xb[1]; sp[2] = xb[2];
    }
    float cx = xb[0], cy = xb[1], cz = xb[2];
    __syncthreads();

    for (int step = 1; step < MM; step++) {
        const int buf = step & 1;
        // ---- update minds (bit-identical per-point math) ----
        u64 ncx2 = pack2(-cx, -cx), ncy2 = pack2(-cy, -cy), ncz2 = pack2(-cz, -cz);
#pragma unroll
        for (int jp = 0; jp < 8; jp++) {
            u64 dx2 = fadd2(px2[jp], ncx2);
            u64 dy2 = fadd2(py2[jp], ncy2);
            u64 dz2 = fadd2(pz2[jp], ncz2);
            u64 d2 = fmul2(dx2, dx2);
            d2 = ffma2(dy2, dy2, d2);
            d2 = ffma2(dz2, dz2, d2);
            float dlo, dhi; unpack2(d2, dlo, dhi);
            mind[jp]     = fminf(mind[jp], dlo);
            mind[jp + 8] = fminf(mind[jp + 8], dhi);
        }
        // ---- thread max via tree (exact) ----
        float mx[8];
#pragma unroll
        for (int i = 0; i < 8; i++) mx[i] = fmaxf(mind[i], mind[i + 8]);
#pragma unroll
        for (int s = 4; s; s >>= 1)
#pragma unroll
            for (int i = 0; i < 4; i++)
                if (i < s) mx[i] = fmaxf(mx[i], mx[i + s]);
        float bv = mx[0];

        unsigned vb = __float_as_uint(bv);                 // distances >= 0
        unsigned wmax = redux_max_u32(vb);
        if (lane == 0) s_val[buf][warp] = wmax;
        __syncthreads();
        if (t == 0) s_win[buf ^ 1] = 0xffffffffu;          // reset prev slot (for step+2)
        unsigned bmax = redux_max_u32(s_val[buf][lane]);
        if (vb == bmax) {                                  // global-max owner(s) only
            unsigned cand = 0xffffffffu;
#pragma unroll
            for (int j = 15; j >= 0; j--)
                if (mind[j] == bv) cand = (unsigned)(t + j * 512);
            atomicMin(&s_win[buf], cand);
        }
        __syncthreads();
        unsigned bix = s_win[buf];

        cx = xb[3 * bix]; cy = xb[3 * bix + 1]; cz = xb[3 * bix + 2];
        if (t == 0) {
            float* sp = g_sub + (size_t)(b * MM + step) * 3;
            sp[0] = cx; sp[1] = cy; sp[2] = cz;
        }
    }
}

// ---------------- grid build (unchanged, proven) ------------------------------
__global__ void __launch_bounds__(512) build_grid_kernel(
    const float* __restrict__ src, int n, int G,
    float4* __restrict__ pts, int* __restrict__ pidx, int* __restrict__ cellstart)
{
    const int b = blockIdx.x;
    const int tid = threadIdx.x;
    const int G3 = G * G * G;
    const float fG = (float)G;
    const float* sp = (src ? src : (const float*)g_sub) + (size_t)b * n * 3;

    __shared__ int hist[512];
    __shared__ int cur[512];
    __shared__ int wsum[16];
    __shared__ short s_cid[8192];

    if (tid < G3) hist[tid] = 0;
    __syncthreads();

    for (int i = tid; i < n; i += 512) {
        const float* p = sp + 3 * i;
        int cx = min(G - 1, max(0, (int)(p[0] * fG)));
        int cy = min(G - 1, max(0, (int)(p[1] * fG)));
        int cz = min(G - 1, max(0, (int)(p[2] * fG)));
        int cid = (cz * G + cy) * G + cx;
        s_cid[i] = (short)cid;
        atomicAdd(&hist[cid], 1);
    }
    __syncthreads();

    int lane = tid & 31, wid = tid >> 5;
    int cnt = (tid < G3) ? hist[tid] : 0;
    int v = cnt;
#pragma unroll
    for (int o = 1; o < 32; o <<= 1) {
        int t2 = __shfl_up_sync(0xffffffffu, v, o);
        if (lane >= o) v += t2;
    }
    if (lane == 31) wsum[wid] = v;
    __syncthreads();
    if (tid == 0) {
        int acc = 0;
        for (int w = 0; w < 16; w++) { int t2 = wsum[w]; wsum[w] = acc; acc += t2; }
    }
    __syncthreads();
    int excl = v - cnt + wsum[wid];
    if (tid < G3) { cellstart[b * (G3 + 1) + tid] = excl; cur[tid] = excl; }
    if (tid == 0) cellstart[b * (G3 + 1) + G3] = n;
    __syncthreads();

    for (int i = tid; i < n; i += 512) {
        int cid = s_cid[i];
        int pos = atomicAdd(&cur[cid], 1);
        const float* p = sp + 3 * i;
        float x0 = p[0], y0 = p[1], z0 = p[2];
        pts[(size_t)b * n + pos] = make_float4(x0, y0, z0, x0 * x0 + y0 * y0 + z0 * z0);
        pidx[(size_t)b * n + pos] = i;
    }
}

// ---------------- KNN: warp/query, coalesced segments, parallel redux merge --
template<int G, int NSRC>
__global__ void __launch_bounds__(256) knn_warp_kernel(
    const float4* __restrict__ pts, const int* __restrict__ pidx,
    const int* __restrict__ cellstart, int* __restrict__ outidx)
{
    constexpr int G3 = G * G * G;
    __shared__ float s_d[KK][256];
    __shared__ int   s_i[KK][256];

    const int tid = threadIdx.x;
    const int lane = tid & 31;
    const int w = tid >> 5;
    const int b = blockIdx.y;
    const int j = blockIdx.x * 8 + w;          // gridded query slot; 250*8 = 2000 = MM
    const float fG = (float)G;

    float4 qp = g_pts2[(size_t)b * MM + j];
    const float qx = qp.x, qy = qp.y, qz = qp.z, qq = qp.w;
    const int cqx = min(G - 1, max(0, (int)(qx * fG)));
    const int cqy = min(G - 1, max(0, (int)(qy * fG)));
    const int cqz = min(G - 1, max(0, (int)(qz * fG)));

    const int* cs = cellstart + b * (G3 + 1);
    const float4* ptsb = pts + (size_t)b * NSRC;
    const int* pidxb = pidx + (size_t)b * NSRC;

    float dist[KK]; int idxr[KK];
#pragma unroll
    for (int r = 0; r < KK; r++) { dist[r] = 1e38f; idxr[r] = 0x7fffffff; }

    for (int R = 1; R <= G; R++) {
        int zlo = max(cqz - R, 0), zhi = min(cqz + R, G - 1);
        int ylo = max(cqy - R, 0), yhi = min(cqy + R, G - 1);
        int xlo = max(cqx - R, 0), xhi = min(cqx + R, G - 1);
        for (int cz = zlo; cz <= zhi; cz++) {
            for (int cy = ylo; cy <= yhi; cy++) {
                bool full = (R == 1) || (cz - cqz == R) || (cqz - cz == R)
                                     || (cy - cqy == R) || (cqy - cy == R);
                int a0 = -1, b0 = -1, a1 = -1, b1 = -1;
                if (full) { a0 = xlo; b0 = xhi; }
                else {
                    if (cqx - R >= 0)     { a0 = cqx - R; b0 = a0; }
                    if (cqx + R <= G - 1) { a1 = cqx + R; b1 = a1; }
                }
                int rowbase = (cz * G + cy) * G;
#pragma unroll
                for (int sg = 0; sg < 2; sg++) {
                    int sa = sg == 0 ? a0 : a1;
                    int sb = sg == 0 ? b0 : b1;
                    if (sa < 0) continue;
                    int beg = cs[rowbase + sa];
                    int end = cs[rowbase + sb + 1];
                    for (int i2 = beg + lane; i2 < end; i2 += 32) {   // coalesced
                        float4 p = ptsb[i2];
                        int id = pidxb[i2];
                        float t2 = qx * p.x;
                        t2 = fmaf(qy, p.y, t2);
                        t2 = fmaf(qz, p.z, t2);
                        float d = fmaf(-2.f, t2, qq + p.w);
                        if (d < dist[KK - 1] ||
                            (d == dist[KK - 1] && id < idxr[KK - 1])) {
                            dist[KK - 1] = d; idxr[KK - 1] = id;
#pragma unroll
                            for (int r = KK - 1; r > 0; --r) {
                                bool sw = (dist[r] < dist[r - 1]) ||
                                          (dist[r] == dist[r - 1] && idxr[r] < idxr[r - 1]);
                                if (sw) {
                                    float td = dist[r]; dist[r] = dist[r - 1]; dist[r - 1] = td;
                                    int ti = idxr[r]; idxr[r] = idxr[r - 1]; idxr[r - 1] = ti;
                                }
                            }
                        }
                    }
                }
            }
        }
        float bnd = R * (1.0f / G);
        bnd = bnd * bnd * 0.9999f;
        unsigned cnt = 0;
#pragma unroll
        for (int r = 0; r < KK; r++) cnt += (dist[r] <= bnd) ? 1u : 0u;
        unsigned total = redux_add_u32(cnt);

        if (total >= (unsigned)KK || R >= G) {
#pragma unroll
            for (int r = 0; r < KK; r++) {
                s_d[r][tid] = dist[r];
                s_i[r][tid] = idxr[r];
            }
            __syncwarp();
            int p = 0;
            float hd = dist[0]; int hid = idxr[0];
            int resi = 0x7fffffff;
#pragma unroll 1
            for (int r = 0; r < KK; r++) {
                unsigned k = fkey(hd);
                unsigned m = redux_min_u32(k);
                unsigned wi = redux_min_u32(k == m ? (unsigned)hid : 0xffffffffu);
                if (lane == r) resi = (int)wi;
                if (k == m && (unsigned)hid == wi) {
                    p++;
                    if (p < KK) { hd = s_d[p][tid]; hid = s_i[p][tid]; }
                    else        { hd = 3e38f; hid = 0x7fffffff; }
                }
            }
            int q = g_pidx2[(size_t)b * MM + j];       // original query index
            if (lane < KK) {
                int ri = min(max(resi, 0), NSRC - 1);  // defensive clamp (no-op when correct)
                outidx[(size_t)(b * MM + q) * KK + lane] = ri;
            }
            break;
        }
    }
}

// ---------------- Layer 1 (unchanged, proven) ---------------------------------
__global__ void __launch_bounds__(128) layer1_kernel(const float* __restrict__ x,
                                                     const float* __restrict__ W1,
                                                     const float* __restrict__ b1) {
    __shared__ float sW[6 * C1W];
    int tid = threadIdx.x;
    for (int i = tid; i < 6 * C1W; i += 128) sW[i] = W1[i];
    __syncthreads();

    int warp = tid >> 5, lane = tid & 31;
    int b = blockIdx.y;
    int m = blockIdx.x * 4 + warp;

    const float* cp = g_sub + (size_t)(b * MM + m) * 3;
    float cx = cp[0], cy = cp[1], cz = cp[2];
    int c0 = lane * 4;
    float bb[4] = { b1[c0], b1[c0 + 1], b1[c0 + 2], b1[c0 + 3] };
    float best[4] = { 0.f, 0.f, 0.f, 0.f };
    const int* ip = g_idx1 + (size_t)(b * MM + m) * KK;

#pragma unroll 1
    for (int k = 0; k < KK; k++) {
        int n = ip[k];
        const float* np = x + ((size_t)b * NN + n) * 3;
        float nx = np[0], ny = np[1], nz = np[2];
        float f[6]; f[0] = nx - cx; f[1] = ny - cy; f[2] = nz - cz; f[3] = nx; f[4] = ny; f[5] = nz;
        float a[4] = { bb[0], bb[1], bb[2], bb[3] };
#pragma unroll
        for (int ff = 0; ff < 6; ff++) {
            const float* w2 = sW + ff * C1W + c0;
            a[0] += f[ff] * w2[0]; a[1] += f[ff] * w2[1];
            a[2] += f[ff] * w2[2]; a[3] += f[ff] * w2[3];
        }
#pragma unroll
        for (int e = 0; e < 4; e++) best[e] = fmaxf(best[e], fmaxf(a[e], 0.f));
    }
    *(float4*)(g_f1 + ((size_t)(b * MM + m) * C1W + c0)) =
        make_float4(best[0], best[1], best[2], best[3]);
}

// ---------------- Layer 2: FFMA2 (unchanged, proven) --------------------------
#define CH 4
__global__ void __launch_bounds__(256, 1) layer2_kernel(const float* __restrict__ b2) {
    __shared__ __align__(16) float sfeat[CH * 16 * 132];
    __shared__ int s_n[CH * 16];

    int b = blockIdx.y, m0 = blockIdx.x * CH;
    int tid = threadIdx.x;

    if (tid < CH * 16) {
        int mm = tid >> 4, k = tid & 15;
        int m = m0 + mm;
        int n = g_idx2[(size_t)(b * MM + m) * KK + k];
        s_n[tid] = n;
        const float* cp = g_sub + (size_t)(b * MM + m) * 3;
        const float* np = g_sub + (size_t)(b * MM + n) * 3;
        float* row = sfeat + tid * 132;
        row[128] = np[0] - cp[0];
        row[129] = np[1] - cp[1];
        row[130] = np[2] - cp[2];
        row[131] = 0.f;
    }
    __syncthreads();
    for (int t = tid; t < CH * 16 * 32; t += 256) {
        int p = t >> 5, fq = t & 31;
        int n = s_n[p];
        float4 v = *(const float4*)(g_f1 + (size_t)(b * MM + n) * C1W + fq * 4);
        *(float4*)(sfeat + p * 132 + fq * 4) = v;
    }
    int c = tid;
    u64 wpk[66];
#pragma unroll
    for (int qd = 0; qd < 33; qd++) {
        float4 w = g_W2q[qd * C2W + c];
        wpk[2 * qd]     = pack2(w.x, w.y);
        wpk[2 * qd + 1] = pack2(w.z, w.w);
    }
    u64 bias = (u64)__float_as_uint(b2[c]);
    __syncthreads();

    float best[CH];
#pragma unroll
    for (int mm = 0; mm < CH; mm++) best[mm] = 0.f;

#pragma unroll 1
    for (int k = 0; k < 16; k++) {
        u64 acc[CH];
#pragma unroll
        for (int mm = 0; mm < CH; mm++) acc[mm] = bias;
#pragma unroll
        for (int q2 = 0; q2 < 33; q2++) {
#pragma unroll
            for (int mm = 0; mm < CH; mm++) {
                const ulonglong2* vrow = (const ulonglong2*)(sfeat + (mm * 16 + k) * 132);
                ulonglong2 v = vrow[q2];
                acc[mm] = ffma2(v.x, wpk[2 * q2], acc[mm]);
                acc[mm] = ffma2(v.y, wpk[2 * q2 + 1], acc[mm]);
            }
        }
#pragma unroll
        for (int mm = 0; mm < CH; mm++) {
            float lo = __uint_as_float((unsigned)(acc[mm] & 0xffffffffu));
            float hi = __uint_as_float((unsigned)(acc[mm] >> 32));
            float a = lo + hi;
            best[mm] = fmaxf(best[mm], fmaxf(a, 0.f));
        }
    }
#pragma unroll
    for (int mm = 0; mm < CH; mm++)
        g_f2[(size_t)(b * MM + m0 + mm) * C2W + c] = best[mm];
}

// ---------------- pool (unchanged, proven) ------------------------------------
__global__ void __launch_bounds__(256) pool_kernel(float* __restrict__ out) {
    int c = threadIdx.x;
    int o = blockIdx.x;
    int b = blockIdx.y;
    const float* f = g_f2 + ((size_t)(b * MM + o * 20) * C2W) + c;
    float mx = -1e38f, sm = 0.f;
#pragma unroll
    for (int w = 0; w < 20; w++) {
        float v = f[(size_t)w * C2W];
        mx = fmaxf(mx, v);
        sm += v;
    }
    out[((size_t)b * C2W + c) * NOUT + o] = mx + sm / 20.0f;
}

// ---------------- launch ------------------------------------------------------
extern "C" void kernel_launch(void* const* d_in, const int* in_sizes, int n_in,
                              void* d_out, int out_size) {
    const float* x  = (const float*)d_in[0];
    const float* W1 = (const float*)d_in[1];
    const float* b1 = (const float*)d_in[2];
    const float* W2 = (const float*)d_in[3];
    const float* b2 = (const float*)d_in[4];
    float* out = (float*)d_out;

    float4* pts1; int* pidx1; int* strt1;
    float4* pts2; int* pidx2; int* strt2;
    int* idx1; int* idx2;
    cudaGetSymbolAddress((void**)&pts1, g_pts1);
    cudaGetSymbolAddress((void**)&pidx1, g_pidx1);
    cudaGetSymbolAddress((void**)&strt1, g_strt1);
    cudaGetSymbolAddress((void**)&pts2, g_pts2);
    cudaGetSymbolAddress((void**)&pidx2, g_pidx2);
    cudaGetSymbolAddress((void**)&strt2, g_strt2);
    cudaGetSymbolAddress((void**)&idx1, g_idx1);
    cudaGetSymbolAddress((void**)&idx2, g_idx2);

    build_grid_kernel<<<BB, 512>>>(x, NN, G1, pts1, pidx1, strt1);   // 0
    w2prep_kernel<<<33, 256>>>(W2);                                  // 1
    filler_kernel<<<1, 256>>>();                                     // 2
    fps_kernel<<<BB, 512>>>(x);                                      // 3 <- profiled slot
    build_grid_kernel<<<BB, 512>>>(nullptr, MM, G2, pts2, pidx2, strt2);            // 4
    knn_warp_kernel<G1, NN><<<dim3(MM / 8, BB), 256>>>(pts1, pidx1, strt1, idx1);   // 5
    knn_warp_kernel<G2, MM><<<dim3(MM / 8, BB), 256>>>(pts2, pidx2, strt2, idx2);   // 6
    layer1_kernel<<<dim3(MM / 4, BB), 128>>>(x, W1, b1);             // 7
    layer2_kernel<<<dim3(MM / CH, BB), 256>>>(b2);                   // 8
    pool_kernel<<<dim3(NOUT, BB), 256>>>(out);                       // 9
}